// round 2
// baseline (speedup 1.0000x reference)
#include <cuda_runtime.h>
#include <math.h>

#define DD 1280
#define NH 8
#define HDIM 160
#define RK 4
#define NB 2
#define SEQ 2048
#define NTOK (NB*SEQ)

// ---- scratch (static __device__ arrays; no allocation) ----
__device__ float g_down[4][RK*DD];
__device__ float g_up[4][RK*DD];
__device__ float g_Weff[4][DD*DD];
__device__ float g_Q[NTOK*DD];
__device__ float g_K[NTOK*DD];
__device__ float g_V[NTOK*DD];
__device__ float g_AO[NTOK*DD];

// ============================================================
// Kernel 0: contract palette into down/up vectors for 4 LoRAs
// down[r*D+i], up[o*RK+r]
// ============================================================
__global__ void k_downup(const float* __restrict__ pal,
    const float* __restrict__ qd, const float* __restrict__ qu,
    const float* __restrict__ kd, const float* __restrict__ ku,
    const float* __restrict__ vd, const float* __restrict__ vu,
    const float* __restrict__ od, const float* __restrict__ ou)
{
    __shared__ float p[15];
    if (threadIdx.x < 15) p[threadIdx.x] = pal[threadIdx.x];
    __syncthreads();
    int idx = blockIdx.x * blockDim.x + threadIdx.x;
    if (idx >= 8 * RK * DD) return;
    int which = idx / (RK * DD);
    int e = idx - which * (RK * DD);
    const float* srcs[8] = {qd, qu, kd, ku, vd, vu, od, ou};
    const float* s = srcs[which];
    float acc = 0.f;
#pragma unroll
    for (int j = 0; j < 15; j++) acc += p[j] * s[e * 15 + j];
    if (which & 1) g_up[which >> 1][e] = acc;
    else          g_down[which >> 1][e] = acc;
}

// ============================================================
// Kernel 1: W_eff = W + up @ down  (rank-4 update, float4)
// ============================================================
__global__ void k_weff(const float* __restrict__ Wq, const float* __restrict__ Wk,
                       const float* __restrict__ Wv, const float* __restrict__ Wo)
{
    const int per_w = DD * DD / 4;       // float4 elements per weight
    int idx = blockIdx.x * blockDim.x + threadIdx.x;
    if (idx >= 4 * per_w) return;
    int w = idx / per_w;
    int e4 = idx - w * per_w;
    int o = e4 / (DD / 4);
    int i4 = e4 - o * (DD / 4);
    const float* Ws[4] = {Wq, Wk, Wv, Wo};
    float4 acc = reinterpret_cast<const float4*>(Ws[w])[e4];
#pragma unroll
    for (int r = 0; r < RK; r++) {
        float u = g_up[w][o * RK + r];
        float4 d = reinterpret_cast<const float4*>(&g_down[w][r * DD])[i4];
        acc.x += u * d.x; acc.y += u * d.y; acc.z += u * d.z; acc.w += u * d.w;
    }
    reinterpret_cast<float4*>(&g_Weff[w][0])[e4] = acc;
}

// ============================================================
// Kernel 2: SGEMM NT  C[M,N] = A[M,K] @ W[N,K]^T (+bias)
// 128x128 tile, BK=8, 256 threads, 8x8 microtile
// M,N,K all multiples of tile sizes here (4096,1280,1280)
// ============================================================
__global__ void __launch_bounds__(256)
sgemm_nt(const float* __restrict__ A, const float* __restrict__ W,
         const float* __restrict__ bias, float* __restrict__ C,
         int M, int N, int K)
{
    __shared__ float As[8][128];
    __shared__ float Bs[8][128];
    int tid = threadIdx.x;
    int lr = tid >> 1;            // 0..127 : tile row loaded by this thread
    int lk = (tid & 1) * 4;       // 0 or 4 : k offset (float4)
    int ty = tid >> 4;            // 0..15
    int tx = tid & 15;            // 0..15

    const float* Ab = A + (size_t)blockIdx.y * 128 * K;
    const float* Wb = W + (size_t)blockIdx.x * 128 * K;

    float acc[8][8];
#pragma unroll
    for (int i = 0; i < 8; i++)
#pragma unroll
        for (int j = 0; j < 8; j++) acc[i][j] = 0.f;

    for (int k0 = 0; k0 < K; k0 += 8) {
        float4 av = *reinterpret_cast<const float4*>(Ab + (size_t)lr * K + k0 + lk);
        float4 wv = *reinterpret_cast<const float4*>(Wb + (size_t)lr * K + k0 + lk);
        __syncthreads();
        As[lk + 0][lr] = av.x; As[lk + 1][lr] = av.y;
        As[lk + 2][lr] = av.z; As[lk + 3][lr] = av.w;
        Bs[lk + 0][lr] = wv.x; Bs[lk + 1][lr] = wv.y;
        Bs[lk + 2][lr] = wv.z; Bs[lk + 3][lr] = wv.w;
        __syncthreads();
#pragma unroll
        for (int k = 0; k < 8; k++) {
            float a[8], b[8];
#pragma unroll
            for (int i = 0; i < 8; i++) a[i] = As[k][ty * 8 + i];
#pragma unroll
            for (int j = 0; j < 8; j++) b[j] = Bs[k][tx * 8 + j];
#pragma unroll
            for (int i = 0; i < 8; i++)
#pragma unroll
                for (int j = 0; j < 8; j++) acc[i][j] += a[i] * b[j];
        }
    }

#pragma unroll
    for (int i = 0; i < 8; i++) {
        size_t row = (size_t)blockIdx.y * 128 + ty * 8 + i;
        int colb = blockIdx.x * 128 + tx * 8;
        float* Cr = C + row * N + colb;
#pragma unroll
        for (int j = 0; j < 8; j += 4) {
            float4 v;
            v.x = acc[i][j + 0]; v.y = acc[i][j + 1];
            v.z = acc[i][j + 2]; v.w = acc[i][j + 3];
            if (bias) {
                v.x += bias[colb + j + 0]; v.y += bias[colb + j + 1];
                v.z += bias[colb + j + 2]; v.w += bias[colb + j + 3];
            }
            *reinterpret_cast<float4*>(Cr + j) = v;
        }
    }
}

// ============================================================
// Kernel 3: flash attention (fp32, online softmax)
// grid (32 q-tiles, 8 heads, 2 batch), 256 threads
// BQ=BK=64, hd=160. Thread(ty,tx): QK rows ty*4+i, cols tx+16j;
// PV rows ty*4+i, cols tx*10+c.
// ============================================================
#define PADH 164
#define PADP 65
#define ATTN_SMEM ((3 * 64 * PADH + 64 * PADP) * 4)

__global__ void __launch_bounds__(256) attn_flash()
{
    extern __shared__ float smf[];
    float* Qs = smf;                      // [64][PADH]
    float* Ks = Qs + 64 * PADH;           // [64][PADH]
    float* Vs = Ks + 64 * PADH;           // [64][PADH]
    float* Ps = Vs + 64 * PADH;           // [64][PADP]

    int qt = blockIdx.x, h = blockIdx.y, b = blockIdx.z;
    int tid = threadIdx.x, ty = tid >> 4, tx = tid & 15;
    const float sc = rsqrtf((float)HDIM);

    size_t qbase = ((size_t)(b * SEQ + qt * 64)) * DD + h * HDIM;
    for (int idx = tid; idx < 64 * HDIM; idx += 256) {
        int r = idx / HDIM, k = idx - r * HDIM;
        Qs[r * PADH + k] = g_Q[qbase + (size_t)r * DD + k] * sc;
    }

    float m[4], l[4], O[4][10];
#pragma unroll
    for (int i = 0; i < 4; i++) {
        m[i] = -1e30f; l[i] = 0.f;
#pragma unroll
        for (int c = 0; c < 10; c++) O[i][c] = 0.f;
    }
    __syncthreads();

    for (int kt = 0; kt < SEQ / 64; kt++) {
        size_t kbase = ((size_t)(b * SEQ + kt * 64)) * DD + h * HDIM;
        for (int idx = tid; idx < 64 * HDIM; idx += 256) {
            int r = idx / HDIM, k = idx - r * HDIM;
            Ks[r * PADH + k] = g_K[kbase + (size_t)r * DD + k];
            Vs[r * PADH + k] = g_V[kbase + (size_t)r * DD + k];
        }
        __syncthreads();

        // --- S = Qs @ Ks^T (64x64x160), 4x4 per thread, float4 k-steps ---
        float s[4][4];
#pragma unroll
        for (int i = 0; i < 4; i++)
#pragma unroll
            for (int j = 0; j < 4; j++) s[i][j] = 0.f;

        for (int k = 0; k < HDIM; k += 4) {
            float4 a[4], bb[4];
#pragma unroll
            for (int i = 0; i < 4; i++)
                a[i] = *reinterpret_cast<const float4*>(&Qs[(ty * 4 + i) * PADH + k]);
#pragma unroll
            for (int j = 0; j < 4; j++)
                bb[j] = *reinterpret_cast<const float4*>(&Ks[(tx + 16 * j) * PADH + k]);
#pragma unroll
            for (int i = 0; i < 4; i++)
#pragma unroll
                for (int j = 0; j < 4; j++) {
                    s[i][j] += a[i].x * bb[j].x + a[i].y * bb[j].y
                             + a[i].z * bb[j].z + a[i].w * bb[j].w;
                }
        }

        // --- online softmax (row groups = 16 lanes sharing ty) ---
#pragma unroll
        for (int i = 0; i < 4; i++) {
            float tm = fmaxf(fmaxf(s[i][0], s[i][1]), fmaxf(s[i][2], s[i][3]));
#pragma unroll
            for (int o = 8; o >= 1; o >>= 1)
                tm = fmaxf(tm, __shfl_xor_sync(0xffffffffu, tm, o));
            float nm = fmaxf(m[i], tm);
            float psum = 0.f;
#pragma unroll
            for (int j = 0; j < 4; j++) {
                float pv = __expf(s[i][j] - nm);
                Ps[(ty * 4 + i) * PADP + tx + 16 * j] = pv;
                psum += pv;
            }
#pragma unroll
            for (int o = 8; o >= 1; o >>= 1)
                psum += __shfl_xor_sync(0xffffffffu, psum, o);
            float al = __expf(m[i] - nm);
            l[i] = l[i] * al + psum;
            m[i] = nm;
#pragma unroll
            for (int c = 0; c < 10; c++) O[i][c] *= al;
        }
        __syncthreads();

        // --- O += P @ V (64x160x64), 4 rows x 10 cols per thread ---
        for (int j = 0; j < 64; j++) {
            float pv[4];
#pragma unroll
            for (int i = 0; i < 4; i++) pv[i] = Ps[(ty * 4 + i) * PADP + j];
            const float* vrow = &Vs[j * PADH + tx * 10];
#pragma unroll
            for (int c = 0; c < 10; c++) {
                float vv = vrow[c];
#pragma unroll
                for (int i = 0; i < 4; i++) O[i][c] += pv[i] * vv;
            }
        }
        __syncthreads();
    }

    // --- normalize + write out ---
#pragma unroll
    for (int i = 0; i < 4; i++) {
        float inv = 1.f / l[i];
        size_t base = ((size_t)(b * SEQ + qt * 64 + ty * 4 + i)) * DD + h * HDIM + tx * 10;
#pragma unroll
        for (int c = 0; c < 10; c++) g_AO[base + c] = O[i][c] * inv;
    }
}

// ============================================================
// host launcher
// ============================================================
extern "C" void kernel_launch(void* const* d_in, const int* in_sizes, int n_in,
                              void* d_out, int out_size)
{
    const float* x   = (const float*)d_in[0];
    const float* pal = (const float*)d_in[1];
    const float* Wq  = (const float*)d_in[2];
    const float* Wk  = (const float*)d_in[3];
    const float* Wv  = (const float*)d_in[4];
    const float* Wo  = (const float*)d_in[5];
    const float* bo  = (const float*)d_in[6];
    const float* qd  = (const float*)d_in[7];
    const float* qu  = (const float*)d_in[8];
    const float* kd  = (const float*)d_in[9];
    const float* ku  = (const float*)d_in[10];
    const float* vd  = (const float*)d_in[11];
    const float* vu  = (const float*)d_in[12];
    const float* od  = (const float*)d_in[13];
    const float* ou  = (const float*)d_in[14];
    float* out = (float*)d_out;

    float *pWeff, *pQ, *pK, *pV, *pAO;
    cudaGetSymbolAddress((void**)&pWeff, g_Weff);
    cudaGetSymbolAddress((void**)&pQ, g_Q);
    cudaGetSymbolAddress((void**)&pK, g_K);
    cudaGetSymbolAddress((void**)&pV, g_V);
    cudaGetSymbolAddress((void**)&pAO, g_AO);

    cudaFuncSetAttribute(attn_flash, cudaFuncAttributeMaxDynamicSharedMemorySize, ATTN_SMEM);

    // 0) palette contractions
    k_downup<<<(8 * RK * DD + 255) / 256, 256>>>(pal, qd, qu, kd, ku, vd, vu, od, ou);
    // 1) effective weights (LoRA folded)
    k_weff<<<(4 * DD * DD / 4 + 255) / 256, 256>>>(Wq, Wk, Wv, Wo);
    // 2) Q,K,V projections
    dim3 gproj(DD / 128, NTOK / 128);
    sgemm_nt<<<gproj, 256>>>(x, pWeff + 0 * DD * DD, nullptr, pQ, NTOK, DD, DD);
    sgemm_nt<<<gproj, 256>>>(x, pWeff + 1 * DD * DD, nullptr, pK, NTOK, DD, DD);
    sgemm_nt<<<gproj, 256>>>(x, pWeff + 2 * DD * DD, nullptr, pV, NTOK, DD, DD);
    // 3) attention
    dim3 gattn(SEQ / 64, NH, NB);
    attn_flash<<<gattn, 256, ATTN_SMEM>>>();
    // 4) output projection + bias
    sgemm_nt<<<gproj, 256>>>(pAO, pWeff + 3 * DD * DD, bo, out, NTOK, DD, DD);
}

// round 6
// speedup vs baseline: 1.5160x; 1.5160x over previous
#include <cuda_runtime.h>
#include <cuda_bf16.h>
#include <math.h>
#include <cstdint>

#define DD 1280
#define NH 8
#define HDIM 160
#define RK 4
#define NB 2
#define SEQ 2048
#define NTOK (NB*SEQ)

// ---- scratch (static __device__ arrays; no allocation) ----
__device__ float g_down[4][RK*DD];
__device__ float g_up[4][RK*DD];
__device__ __nv_bfloat16 g_Whi[4][DD*DD];
__device__ __nv_bfloat16 g_Wlo[4][DD*DD];
__device__ __nv_bfloat16 g_Ahi[NTOK*DD];
__device__ __nv_bfloat16 g_Alo[NTOK*DD];
__device__ float g_Q[NTOK*DD];
__device__ float g_K[NTOK*DD];
__device__ float g_V[NTOK*DD];
__device__ float g_AO[NTOK*DD];

// ============================================================
// helpers: cp.async, ldmatrix, mma (all family-portable, sm_80+)
// ============================================================
__device__ __forceinline__ uint32_t smem_u32(const void* p) {
    uint32_t a;
    asm("{ .reg .u64 t; cvta.to.shared.u64 t, %1; cvt.u32.u64 %0, t; }" : "=r"(a) : "l"(p));
    return a;
}
__device__ __forceinline__ void cp16(uint32_t dst, const void* src) {
    asm volatile("cp.async.cg.shared.global [%0], [%1], 16;" :: "r"(dst), "l"(src) : "memory");
}
#define CP_COMMIT() asm volatile("cp.async.commit_group;" ::: "memory")
#define CP_WAIT(n)  asm volatile("cp.async.wait_group %0;" :: "n"(n) : "memory")

__device__ __forceinline__ void ldsm4(uint32_t* r, uint32_t addr) {
    asm volatile("ldmatrix.sync.aligned.m8n8.x4.shared.b16 {%0,%1,%2,%3}, [%4];"
        : "=r"(r[0]), "=r"(r[1]), "=r"(r[2]), "=r"(r[3]) : "r"(addr));
}
__device__ __forceinline__ void mma16816(float* d, const uint32_t* a, const uint32_t* b) {
    asm volatile(
        "mma.sync.aligned.m16n8k16.row.col.f32.bf16.bf16.f32 "
        "{%0,%1,%2,%3}, {%4,%5,%6,%7}, {%8,%9}, {%0,%1,%2,%3};"
        : "+f"(d[0]), "+f"(d[1]), "+f"(d[2]), "+f"(d[3])
        : "r"(a[0]), "r"(a[1]), "r"(a[2]), "r"(a[3]), "r"(b[0]), "r"(b[1]));
}

// ============================================================
// Kernel 0: contract palette into down/up vectors for 4 LoRAs
// ============================================================
__global__ void k_downup(const float* __restrict__ pal,
    const float* __restrict__ qd, const float* __restrict__ qu,
    const float* __restrict__ kd, const float* __restrict__ ku,
    const float* __restrict__ vd, const float* __restrict__ vu,
    const float* __restrict__ od, const float* __restrict__ ou)
{
    __shared__ float p[15];
    if (threadIdx.x < 15) p[threadIdx.x] = pal[threadIdx.x];
    __syncthreads();
    int idx = blockIdx.x * blockDim.x + threadIdx.x;
    if (idx >= 8 * RK * DD) return;
    int which = idx / (RK * DD);
    int e = idx - which * (RK * DD);
    const float* srcs[8] = {qd, qu, kd, ku, vd, vu, od, ou};
    const float* s = srcs[which];
    float acc = 0.f;
#pragma unroll
    for (int j = 0; j < 15; j++) acc += p[j] * s[e * 15 + j];
    if (which & 1) g_up[which >> 1][e] = acc;
    else          g_down[which >> 1][e] = acc;
}

// ============================================================
// Kernel 1: W_eff = W + up @ down, written as bf16 hi/lo pair
// ============================================================
__global__ void k_weff(const float* __restrict__ Wq, const float* __restrict__ Wk,
                       const float* __restrict__ Wv, const float* __restrict__ Wo)
{
    const int per_w = DD * DD / 4;
    int idx = blockIdx.x * blockDim.x + threadIdx.x;
    if (idx >= 4 * per_w) return;
    int w = idx / per_w;
    int e4 = idx - w * per_w;
    int o = e4 / (DD / 4);
    int i4 = e4 - o * (DD / 4);
    const float* Ws[4] = {Wq, Wk, Wv, Wo};
    float4 acc = reinterpret_cast<const float4*>(Ws[w])[e4];
#pragma unroll
    for (int r = 0; r < RK; r++) {
        float u = g_up[w][o * RK + r];
        float4 d = reinterpret_cast<const float4*>(&g_down[w][r * DD])[i4];
        acc.x += u * d.x; acc.y += u * d.y; acc.z += u * d.z; acc.w += u * d.w;
    }
    float v[4] = {acc.x, acc.y, acc.z, acc.w};
    __nv_bfloat16 h[4], l[4];
#pragma unroll
    for (int j = 0; j < 4; j++) {
        h[j] = __float2bfloat16(v[j]);
        l[j] = __float2bfloat16(v[j] - __bfloat162float(h[j]));
    }
    reinterpret_cast<__nv_bfloat162*>(&g_Whi[w][0])[2*e4]   = __nv_bfloat162(h[0], h[1]);
    reinterpret_cast<__nv_bfloat162*>(&g_Whi[w][0])[2*e4+1] = __nv_bfloat162(h[2], h[3]);
    reinterpret_cast<__nv_bfloat162*>(&g_Wlo[w][0])[2*e4]   = __nv_bfloat162(l[0], l[1]);
    reinterpret_cast<__nv_bfloat162*>(&g_Wlo[w][0])[2*e4+1] = __nv_bfloat162(l[2], l[3]);
}

// ============================================================
// Kernel 1b: fp32 activation -> bf16 hi/lo pair
// ============================================================
__global__ void k_cvtA(const float* __restrict__ src)
{
    int i = blockIdx.x * blockDim.x + threadIdx.x;
    if (i >= NTOK * DD / 4) return;
    float4 a = reinterpret_cast<const float4*>(src)[i];
    float v[4] = {a.x, a.y, a.z, a.w};
    __nv_bfloat16 h[4], l[4];
#pragma unroll
    for (int j = 0; j < 4; j++) {
        h[j] = __float2bfloat16(v[j]);
        l[j] = __float2bfloat16(v[j] - __bfloat162float(h[j]));
    }
    reinterpret_cast<__nv_bfloat162*>(g_Ahi)[2*i]   = __nv_bfloat162(h[0], h[1]);
    reinterpret_cast<__nv_bfloat162*>(g_Ahi)[2*i+1] = __nv_bfloat162(h[2], h[3]);
    reinterpret_cast<__nv_bfloat162*>(g_Alo)[2*i]   = __nv_bfloat162(l[0], l[1]);
    reinterpret_cast<__nv_bfloat162*>(g_Alo)[2*i+1] = __nv_bfloat162(l[2], l[3]);
}

// ============================================================
// Kernel 2: mma.sync split-bf16 GEMM  C[M,N] = A @ W^T (+bias)
// 128x128 tile, BK=32, 8 warps (4x2), warp tile 32x64.
// smem rows padded to 80B -> ldmatrix conflict-free.
// cp.async double buffer. 3 passes: Ah*Wh + Ah*Wl + Al*Wh.
// ============================================================
#define BK 32
#define TSTRIDE 80
#define TILEB (128 * TSTRIDE)       // 10240
#define STAGEB (4 * TILEB)          // 40960
#define GEMM_SMEM (2 * STAGEB)      // 81920
#define NCHUNK (DD / BK)            // 40

__global__ void __launch_bounds__(256, 2)
gemm_tc(const __nv_bfloat16* __restrict__ Ahi, const __nv_bfloat16* __restrict__ Alo,
        const __nv_bfloat16* __restrict__ Whi, const __nv_bfloat16* __restrict__ Wlo,
        const float* __restrict__ bias, float* __restrict__ C)
{
    extern __shared__ char smem[];
    const uint32_t sbase = smem_u32(smem);
    const int tid = threadIdx.x;
    const int lane = tid & 31, wid = tid >> 5;
    const int warp_m = (wid & 3) * 32, warp_n = (wid >> 2) * 64;
    const int K = DD, N = DD;
    const size_t tileM = (size_t)blockIdx.y * 128;
    const size_t tileN = (size_t)blockIdx.x * 128;

    const __nv_bfloat16* srcs[4] = {Ahi, Alo, Whi, Wlo};

    // ---- gmem -> smem loader: 2048 x 16B per stage, 8 per thread ----
    auto load_stage = [&](int kc, int s) {
        const int kcol = kc * BK;
        uint32_t dst0 = sbase + s * STAGEB;
#pragma unroll
        for (int i = 0; i < 8; i++) {
            int idx = i * 256 + tid;          // tile(4) x row(128) x chunk(4)
            int t = idx >> 9;
            int rem = idx & 511;
            int r = rem >> 2, c = rem & 3;
            size_t grow = (t < 2) ? (tileM + r) : (tileN + r);
            const __nv_bfloat16* src = srcs[t] + grow * K + kcol + c * 8;
            cp16(dst0 + t * TILEB + r * TSTRIDE + c * 16, src);
        }
        CP_COMMIT();
    };

    float acc[2][8][4];
#pragma unroll
    for (int mf = 0; mf < 2; mf++)
#pragma unroll
        for (int nf = 0; nf < 8; nf++)
#pragma unroll
            for (int j = 0; j < 4; j++) acc[mf][nf][j] = 0.f;

    load_stage(0, 0);

    // fragment smem addresses (lane-dependent parts precomputed)
    const int a_row = warp_m + ((lane >> 3) & 1) * 8 + (lane & 7);
    const uint32_t a_off = (uint32_t)(a_row * TSTRIDE + (lane >> 4) * 16);
    const int b_row = warp_n + ((lane >> 4) & 1) * 8 + (lane & 7);
    const uint32_t b_off = (uint32_t)(b_row * TSTRIDE + ((lane >> 3) & 1) * 16);

    for (int kc = 0; kc < NCHUNK; kc++) {
        const int s = kc & 1;
        if (kc + 1 < NCHUNK) {
            load_stage(kc + 1, s ^ 1);
            CP_WAIT(1);
        } else {
            CP_WAIT(0);
        }
        __syncthreads();

        const uint32_t stage = sbase + s * STAGEB;
#pragma unroll
        for (int ks = 0; ks < 2; ks++) {
            const uint32_t kb = ks * 32;
            uint32_t ah[2][4], al[2][4];
#pragma unroll
            for (int mf = 0; mf < 2; mf++) {
                ldsm4(ah[mf], stage + a_off + mf * (16 * TSTRIDE) + kb);
                ldsm4(al[mf], stage + TILEB + a_off + mf * (16 * TSTRIDE) + kb);
            }
#pragma unroll
            for (int np = 0; np < 4; np++) {
                uint32_t bh[4], bl[4];
                ldsm4(bh, stage + 2 * TILEB + b_off + np * (16 * TSTRIDE) + kb);
                ldsm4(bl, stage + 3 * TILEB + b_off + np * (16 * TSTRIDE) + kb);
#pragma unroll
                for (int mf = 0; mf < 2; mf++) {
#pragma unroll
                    for (int half = 0; half < 2; half++) {
                        float* d = acc[mf][np * 2 + half];
                        mma16816(d, ah[mf], bh + half * 2);
                        mma16816(d, ah[mf], bl + half * 2);
                        mma16816(d, al[mf], bh + half * 2);
                    }
                }
            }
        }
        __syncthreads();
    }

    // ---- epilogue: direct fp32 stores ----
    const int er = lane >> 2;            // 0..7
    const int ec = (lane & 3) * 2;       // 0,2,4,6
#pragma unroll
    for (int mf = 0; mf < 2; mf++) {
        size_t row0 = tileM + warp_m + mf * 16 + er;
#pragma unroll
        for (int nf = 0; nf < 8; nf++) {
            size_t col = tileN + warp_n + nf * 8 + ec;
            float bx = 0.f, by = 0.f;
            if (bias) { bx = bias[col]; by = bias[col + 1]; }
            float2 v0 = {acc[mf][nf][0] + bx, acc[mf][nf][1] + by};
            float2 v1 = {acc[mf][nf][2] + bx, acc[mf][nf][3] + by};
            *reinterpret_cast<float2*>(C + row0 * N + col) = v0;
            *reinterpret_cast<float2*>(C + (row0 + 8) * N + col) = v1;
        }
    }
}

// ============================================================
// Kernel 3: flash attention (fp32, online softmax) — unchanged
// ============================================================
#define PADH 164
#define PADP 65
#define ATTN_SMEM ((3 * 64 * PADH + 64 * PADP) * 4)

__global__ void __launch_bounds__(256) attn_flash()
{
    extern __shared__ float smf[];
    float* Qs = smf;
    float* Ks = Qs + 64 * PADH;
    float* Vs = Ks + 64 * PADH;
    float* Ps = Vs + 64 * PADH;

    int qt = blockIdx.x, h = blockIdx.y, b = blockIdx.z;
    int tid = threadIdx.x, ty = tid >> 4, tx = tid & 15;
    const float sc = rsqrtf((float)HDIM);

    size_t qbase = ((size_t)(b * SEQ + qt * 64)) * DD + h * HDIM;
    for (int idx = tid; idx < 64 * HDIM; idx += 256) {
        int r = idx / HDIM, k = idx - r * HDIM;
        Qs[r * PADH + k] = g_Q[qbase + (size_t)r * DD + k] * sc;
    }

    float m[4], l[4], O[4][10];
#pragma unroll
    for (int i = 0; i < 4; i++) {
        m[i] = -1e30f; l[i] = 0.f;
#pragma unroll
        for (int c = 0; c < 10; c++) O[i][c] = 0.f;
    }
    __syncthreads();

    for (int kt = 0; kt < SEQ / 64; kt++) {
        size_t kbase = ((size_t)(b * SEQ + kt * 64)) * DD + h * HDIM;
        for (int idx = tid; idx < 64 * HDIM; idx += 256) {
            int r = idx / HDIM, k = idx - r * HDIM;
            Ks[r * PADH + k] = g_K[kbase + (size_t)r * DD + k];
            Vs[r * PADH + k] = g_V[kbase + (size_t)r * DD + k];
        }
        __syncthreads();

        float s[4][4];
#pragma unroll
        for (int i = 0; i < 4; i++)
#pragma unroll
            for (int j = 0; j < 4; j++) s[i][j] = 0.f;

        for (int k = 0; k < HDIM; k += 4) {
            float4 a[4], bb[4];
#pragma unroll
            for (int i = 0; i < 4; i++)
                a[i] = *reinterpret_cast<const float4*>(&Qs[(ty * 4 + i) * PADH + k]);
#pragma unroll
            for (int j = 0; j < 4; j++)
                bb[j] = *reinterpret_cast<const float4*>(&Ks[(tx + 16 * j) * PADH + k]);
#pragma unroll
            for (int i = 0; i < 4; i++)
#pragma unroll
                for (int j = 0; j < 4; j++) {
                    s[i][j] += a[i].x * bb[j].x + a[i].y * bb[j].y
                             + a[i].z * bb[j].z + a[i].w * bb[j].w;
                }
        }

#pragma unroll
        for (int i = 0; i < 4; i++) {
            float tm = fmaxf(fmaxf(s[i][0], s[i][1]), fmaxf(s[i][2], s[i][3]));
#pragma unroll
            for (int o = 8; o >= 1; o >>= 1)
                tm = fmaxf(tm, __shfl_xor_sync(0xffffffffu, tm, o));
            float nm = fmaxf(m[i], tm);
            float psum = 0.f;
#pragma unroll
            for (int j = 0; j < 4; j++) {
                float pv = __expf(s[i][j] - nm);
                Ps[(ty * 4 + i) * PADP + tx + 16 * j] = pv;
                psum += pv;
            }
#pragma unroll
            for (int o = 8; o >= 1; o >>= 1)
                psum += __shfl_xor_sync(0xffffffffu, psum, o);
            float al = __expf(m[i] - nm);
            l[i] = l[i] * al + psum;
            m[i] = nm;
#pragma unroll
            for (int c = 0; c < 10; c++) O[i][c] *= al;
        }
        __syncthreads();

        for (int j = 0; j < 64; j++) {
            float pv[4];
#pragma unroll
            for (int i = 0; i < 4; i++) pv[i] = Ps[(ty * 4 + i) * PADP + j];
            const float* vrow = &Vs[j * PADH + tx * 10];
#pragma unroll
            for (int c = 0; c < 10; c++) {
                float vv = vrow[c];
#pragma unroll
                for (int i = 0; i < 4; i++) O[i][c] += pv[i] * vv;
            }
        }
        __syncthreads();
    }

#pragma unroll
    for (int i = 0; i < 4; i++) {
        float inv = 1.f / l[i];
        size_t base = ((size_t)(b * SEQ + qt * 64 + ty * 4 + i)) * DD + h * HDIM + tx * 10;
#pragma unroll
        for (int c = 0; c < 10; c++) g_AO[base + c] = O[i][c] * inv;
    }
}

// ============================================================
// host launcher
// ============================================================
extern "C" void kernel_launch(void* const* d_in, const int* in_sizes, int n_in,
                              void* d_out, int out_size)
{
    const float* x   = (const float*)d_in[0];
    const float* pal = (const float*)d_in[1];
    const float* Wq  = (const float*)d_in[2];
    const float* Wk  = (const float*)d_in[3];
    const float* Wv  = (const float*)d_in[4];
    const float* Wo  = (const float*)d_in[5];
    const float* bo  = (const float*)d_in[6];
    const float* qd  = (const float*)d_in[7];
    const float* qu  = (const float*)d_in[8];
    const float* kd  = (const float*)d_in[9];
    const float* ku  = (const float*)d_in[10];
    const float* vd  = (const float*)d_in[11];
    const float* vu  = (const float*)d_in[12];
    const float* od  = (const float*)d_in[13];
    const float* ou  = (const float*)d_in[14];
    float* out = (float*)d_out;

    __nv_bfloat16 *pWhi, *pWlo, *pAhi, *pAlo;
    float *pQ, *pK, *pV, *pAO;
    cudaGetSymbolAddress((void**)&pWhi, g_Whi);
    cudaGetSymbolAddress((void**)&pWlo, g_Wlo);
    cudaGetSymbolAddress((void**)&pAhi, g_Ahi);
    cudaGetSymbolAddress((void**)&pAlo, g_Alo);
    cudaGetSymbolAddress((void**)&pQ, g_Q);
    cudaGetSymbolAddress((void**)&pK, g_K);
    cudaGetSymbolAddress((void**)&pV, g_V);
    cudaGetSymbolAddress((void**)&pAO, g_AO);

    cudaFuncSetAttribute(attn_flash, cudaFuncAttributeMaxDynamicSharedMemorySize, ATTN_SMEM);
    cudaFuncSetAttribute(gemm_tc, cudaFuncAttributeMaxDynamicSharedMemorySize, GEMM_SMEM);

    const size_t WSZ = (size_t)DD * DD;

    // 0) palette contractions
    k_downup<<<(8 * RK * DD + 255) / 256, 256>>>(pal, qd, qu, kd, ku, vd, vu, od, ou);
    // 1) effective weights (LoRA folded) -> bf16 hi/lo
    k_weff<<<(4 * DD * DD / 4 + 255) / 256, 256>>>(Wq, Wk, Wv, Wo);
    // 1b) x -> bf16 hi/lo
    k_cvtA<<<(NTOK * DD / 4 + 255) / 256, 256>>>(x);
    // 2) Q,K,V projections (tensor cores)
    dim3 gg(DD / 128, NTOK / 128);
    gemm_tc<<<gg, 256, GEMM_SMEM>>>(pAhi, pAlo, pWhi + 0 * WSZ, pWlo + 0 * WSZ, nullptr, pQ);
    gemm_tc<<<gg, 256, GEMM_SMEM>>>(pAhi, pAlo, pWhi + 1 * WSZ, pWlo + 1 * WSZ, nullptr, pK);
    gemm_tc<<<gg, 256, GEMM_SMEM>>>(pAhi, pAlo, pWhi + 2 * WSZ, pWlo + 2 * WSZ, nullptr, pV);
    // 3) attention
    dim3 gattn(SEQ / 64, NH, NB);
    attn_flash<<<gattn, 256, ATTN_SMEM>>>();
    // 4) AO -> bf16 hi/lo, then output projection + bias (tensor cores)
    k_cvtA<<<(NTOK * DD / 4 + 255) / 256, 256>>>(pAO);
    gemm_tc<<<gg, 256, GEMM_SMEM>>>(pAhi, pAlo, pWhi + 3 * WSZ, pWlo + 3 * WSZ, bo, out);
}

// round 9
// speedup vs baseline: 3.8383x; 2.5319x over previous
#include <cuda_runtime.h>
#include <cuda_bf16.h>
#include <math.h>
#include <cstdint>

#define DD 1280
#define NH 8
#define HDIM 160
#define RK 4
#define NB 2
#define SEQ 2048
#define NTOK (NB*SEQ)

// ---- scratch (static __device__ arrays; no allocation) ----
__device__ float g_down[4][RK*DD];
__device__ float g_up[4][RK*DD];
__device__ __nv_bfloat16 g_Whi[4][DD*DD];
__device__ __nv_bfloat16 g_Wlo[4][DD*DD];
__device__ __nv_bfloat16 g_Ahi[NTOK*DD];
__device__ __nv_bfloat16 g_Alo[NTOK*DD];
__device__ __nv_bfloat16 g_Qh[NTOK*DD];
__device__ __nv_bfloat16 g_Ql[NTOK*DD];
__device__ __nv_bfloat16 g_Kh[NTOK*DD];
__device__ __nv_bfloat16 g_Kl[NTOK*DD];
__device__ __nv_bfloat16 g_Vh[NTOK*DD];
__device__ __nv_bfloat16 g_Vl[NTOK*DD];
__device__ __nv_bfloat16 g_AOh[NTOK*DD];
__device__ __nv_bfloat16 g_AOl[NTOK*DD];

// ============================================================
// helpers (family-portable, sm_80+)
// ============================================================
__device__ __forceinline__ uint32_t smem_u32(const void* p) {
    uint32_t a;
    asm("{ .reg .u64 t; cvta.to.shared.u64 t, %1; cvt.u32.u64 %0, t; }" : "=r"(a) : "l"(p));
    return a;
}
__device__ __forceinline__ void cp16(uint32_t dst, const void* src) {
    asm volatile("cp.async.cg.shared.global [%0], [%1], 16;" :: "r"(dst), "l"(src) : "memory");
}
#define CP_COMMIT() asm volatile("cp.async.commit_group;" ::: "memory")
#define CP_WAIT(n)  asm volatile("cp.async.wait_group %0;" :: "n"(n) : "memory")

__device__ __forceinline__ void ldsm4(uint32_t* r, uint32_t addr) {
    asm volatile("ldmatrix.sync.aligned.m8n8.x4.shared.b16 {%0,%1,%2,%3}, [%4];"
        : "=r"(r[0]), "=r"(r[1]), "=r"(r[2]), "=r"(r[3]) : "r"(addr));
}
__device__ __forceinline__ void ldsm4t(uint32_t* r, uint32_t addr) {
    asm volatile("ldmatrix.sync.aligned.m8n8.x4.trans.shared.b16 {%0,%1,%2,%3}, [%4];"
        : "=r"(r[0]), "=r"(r[1]), "=r"(r[2]), "=r"(r[3]) : "r"(addr));
}
__device__ __forceinline__ void mma16816(float* d, const uint32_t* a, const uint32_t* b) {
    asm volatile(
        "mma.sync.aligned.m16n8k16.row.col.f32.bf16.bf16.f32 "
        "{%0,%1,%2,%3}, {%4,%5,%6,%7}, {%8,%9}, {%0,%1,%2,%3};"
        : "+f"(d[0]), "+f"(d[1]), "+f"(d[2]), "+f"(d[3])
        : "r"(a[0]), "r"(a[1]), "r"(a[2]), "r"(a[3]), "r"(b[0]), "r"(b[1]));
}
__device__ __forceinline__ float ex2f(float x) {
    float y; asm("ex2.approx.f32 %0, %1;" : "=f"(y) : "f"(x)); return y;
}
__device__ __forceinline__ uint32_t pack2(float a, float b) {
    __nv_bfloat162 v = __floats2bfloat162_rn(a, b);
    return reinterpret_cast<uint32_t&>(v);
}
__device__ __forceinline__ float res_lo(float f) {
    return f - __bfloat162float(__float2bfloat16(f));
}

// ============================================================
// Kernel 0: contract palette into down/up vectors for 4 LoRAs
// ============================================================
__global__ void k_downup(const float* __restrict__ pal,
    const float* __restrict__ qd, const float* __restrict__ qu,
    const float* __restrict__ kd, const float* __restrict__ ku,
    const float* __restrict__ vd, const float* __restrict__ vu,
    const float* __restrict__ od, const float* __restrict__ ou)
{
    __shared__ float p[15];
    if (threadIdx.x < 15) p[threadIdx.x] = pal[threadIdx.x];
    __syncthreads();
    int idx = blockIdx.x * blockDim.x + threadIdx.x;
    if (idx >= 8 * RK * DD) return;
    int which = idx / (RK * DD);
    int e = idx - which * (RK * DD);
    const float* srcs[8] = {qd, qu, kd, ku, vd, vu, od, ou};
    const float* s = srcs[which];
    float acc = 0.f;
#pragma unroll
    for (int j = 0; j < 15; j++) acc += p[j] * s[e * 15 + j];
    if (which & 1) g_up[which >> 1][e] = acc;
    else          g_down[which >> 1][e] = acc;
}

// ============================================================
// Kernel 1: W_eff = W + up @ down, written as bf16 hi/lo pair
// ============================================================
__global__ void k_weff(const float* __restrict__ Wq, const float* __restrict__ Wk,
                       const float* __restrict__ Wv, const float* __restrict__ Wo)
{
    const int per_w = DD * DD / 4;
    int idx = blockIdx.x * blockDim.x + threadIdx.x;
    if (idx >= 4 * per_w) return;
    int w = idx / per_w;
    int e4 = idx - w * per_w;
    int o = e4 / (DD / 4);
    int i4 = e4 - o * (DD / 4);
    const float* Ws[4] = {Wq, Wk, Wv, Wo};
    float4 acc = reinterpret_cast<const float4*>(Ws[w])[e4];
#pragma unroll
    for (int r = 0; r < RK; r++) {
        float u = g_up[w][o * RK + r];
        float4 d = reinterpret_cast<const float4*>(&g_down[w][r * DD])[i4];
        acc.x += u * d.x; acc.y += u * d.y; acc.z += u * d.z; acc.w += u * d.w;
    }
    float v[4] = {acc.x, acc.y, acc.z, acc.w};
    reinterpret_cast<uint32_t*>(&g_Whi[w][0])[2*e4]   = pack2(v[0], v[1]);
    reinterpret_cast<uint32_t*>(&g_Whi[w][0])[2*e4+1] = pack2(v[2], v[3]);
    reinterpret_cast<uint32_t*>(&g_Wlo[w][0])[2*e4]   = pack2(res_lo(v[0]), res_lo(v[1]));
    reinterpret_cast<uint32_t*>(&g_Wlo[w][0])[2*e4+1] = pack2(res_lo(v[2]), res_lo(v[3]));
}

// ============================================================
// Kernel 1b: fp32 activation -> bf16 hi/lo pair (input x only)
// ============================================================
__global__ void k_cvtA(const float* __restrict__ src)
{
    int i = blockIdx.x * blockDim.x + threadIdx.x;
    if (i >= NTOK * DD / 4) return;
    float4 a = reinterpret_cast<const float4*>(src)[i];
    float v[4] = {a.x, a.y, a.z, a.w};
    reinterpret_cast<uint32_t*>(g_Ahi)[2*i]   = pack2(v[0], v[1]);
    reinterpret_cast<uint32_t*>(g_Ahi)[2*i+1] = pack2(v[2], v[3]);
    reinterpret_cast<uint32_t*>(g_Alo)[2*i]   = pack2(res_lo(v[0]), res_lo(v[1]));
    reinterpret_cast<uint32_t*>(g_Alo)[2*i+1] = pack2(res_lo(v[2]), res_lo(v[3]));
}

// ============================================================
// Kernel 2: mma.sync split-bf16 GEMM  C = A @ W^T
// output: fp32 + bias (Cf != null)  OR  bf16 hi/lo pair (Ch, Cl)
// ============================================================
#define BK 32
#define TSTRIDE 80
#define TILEB (128 * TSTRIDE)
#define STAGEB (4 * TILEB)
#define GEMM_SMEM (2 * STAGEB)
#define NCHUNK (DD / BK)

__global__ void __launch_bounds__(256, 2)
gemm_tc(const __nv_bfloat16* __restrict__ Ahi, const __nv_bfloat16* __restrict__ Alo,
        const __nv_bfloat16* __restrict__ Whi, const __nv_bfloat16* __restrict__ Wlo,
        const float* __restrict__ bias, float* __restrict__ Cf,
        __nv_bfloat16* __restrict__ Ch, __nv_bfloat16* __restrict__ Cl)
{
    extern __shared__ char smem[];
    const uint32_t sbase = smem_u32(smem);
    const int tid = threadIdx.x;
    const int lane = tid & 31, wid = tid >> 5;
    const int warp_m = (wid & 3) * 32, warp_n = (wid >> 2) * 64;
    const int K = DD, N = DD;
    const size_t tileM = (size_t)blockIdx.y * 128;
    const size_t tileN = (size_t)blockIdx.x * 128;

    const __nv_bfloat16* srcs[4] = {Ahi, Alo, Whi, Wlo};

    auto load_stage = [&](int kc, int s) {
        const int kcol = kc * BK;
        uint32_t dst0 = sbase + s * STAGEB;
#pragma unroll
        for (int i = 0; i < 8; i++) {
            int idx = i * 256 + tid;
            int t = idx >> 9;
            int rem = idx & 511;
            int r = rem >> 2, c = rem & 3;
            size_t grow = (t < 2) ? (tileM + r) : (tileN + r);
            const __nv_bfloat16* src = srcs[t] + grow * K + kcol + c * 8;
            cp16(dst0 + t * TILEB + r * TSTRIDE + c * 16, src);
        }
        CP_COMMIT();
    };

    float acc[2][8][4];
#pragma unroll
    for (int mf = 0; mf < 2; mf++)
#pragma unroll
        for (int nf = 0; nf < 8; nf++)
#pragma unroll
            for (int j = 0; j < 4; j++) acc[mf][nf][j] = 0.f;

    load_stage(0, 0);

    const int a_row = warp_m + ((lane >> 3) & 1) * 8 + (lane & 7);
    const uint32_t a_off = (uint32_t)(a_row * TSTRIDE + (lane >> 4) * 16);
    const int b_row = warp_n + ((lane >> 4) & 1) * 8 + (lane & 7);
    const uint32_t b_off = (uint32_t)(b_row * TSTRIDE + ((lane >> 3) & 1) * 16);

    for (int kc = 0; kc < NCHUNK; kc++) {
        const int s = kc & 1;
        if (kc + 1 < NCHUNK) { load_stage(kc + 1, s ^ 1); CP_WAIT(1); }
        else { CP_WAIT(0); }
        __syncthreads();

        const uint32_t stage = sbase + s * STAGEB;
#pragma unroll
        for (int ks = 0; ks < 2; ks++) {
            const uint32_t kb = ks * 32;
            uint32_t ah[2][4], al[2][4];
#pragma unroll
            for (int mf = 0; mf < 2; mf++) {
                ldsm4(ah[mf], stage + a_off + mf * (16 * TSTRIDE) + kb);
                ldsm4(al[mf], stage + TILEB + a_off + mf * (16 * TSTRIDE) + kb);
            }
#pragma unroll
            for (int np = 0; np < 4; np++) {
                uint32_t bh[4], bl[4];
                ldsm4(bh, stage + 2 * TILEB + b_off + np * (16 * TSTRIDE) + kb);
                ldsm4(bl, stage + 3 * TILEB + b_off + np * (16 * TSTRIDE) + kb);
#pragma unroll
                for (int mf = 0; mf < 2; mf++) {
#pragma unroll
                    for (int half = 0; half < 2; half++) {
                        float* d = acc[mf][np * 2 + half];
                        mma16816(d, ah[mf], bh + half * 2);
                        mma16816(d, ah[mf], bl + half * 2);
                        mma16816(d, al[mf], bh + half * 2);
                    }
                }
            }
        }
        __syncthreads();
    }

    const int er = lane >> 2;
    const int ec = (lane & 3) * 2;
#pragma unroll
    for (int mf = 0; mf < 2; mf++) {
        size_t row0 = tileM + warp_m + mf * 16 + er;
#pragma unroll
        for (int nf = 0; nf < 8; nf++) {
            size_t col = tileN + warp_n + nf * 8 + ec;
            float f0 = acc[mf][nf][0], f1 = acc[mf][nf][1];
            float f2 = acc[mf][nf][2], f3 = acc[mf][nf][3];
            if (Cf) {
                float bx = 0.f, by = 0.f;
                if (bias) { bx = bias[col]; by = bias[col + 1]; }
                float2 v0 = {f0 + bx, f1 + by};
                float2 v1 = {f2 + bx, f3 + by};
                *reinterpret_cast<float2*>(Cf + row0 * N + col) = v0;
                *reinterpret_cast<float2*>(Cf + (row0 + 8) * N + col) = v1;
            } else {
                *reinterpret_cast<uint32_t*>(Ch + row0 * N + col)       = pack2(f0, f1);
                *reinterpret_cast<uint32_t*>(Cl + row0 * N + col)       = pack2(res_lo(f0), res_lo(f1));
                *reinterpret_cast<uint32_t*>(Ch + (row0 + 8) * N + col) = pack2(f2, f3);
                *reinterpret_cast<uint32_t*>(Cl + (row0 + 8) * N + col) = pack2(res_lo(f2), res_lo(f3));
            }
        }
    }
}

// ============================================================
// Kernel 3: flash attention on tensor cores (split-bf16, FA2)
// BQ=128, BK=64, hd=160. 8 warps x 16 rows. grid (16, 8, 2).
// ============================================================
#define AQ_STR 168                 // elems; 336 B row stride
#define AQ_ROWB (AQ_STR * 2)       // 336
#define Q_TILEB (128 * AQ_ROWB)    // 43008
#define KV_TILEB (64 * AQ_ROWB)    // 21504
#define ATTN_SMEM (2 * Q_TILEB + 4 * KV_TILEB)   // 172032

__global__ void __launch_bounds__(256) attn_tc()
{
    extern __shared__ char sm[];
    const uint32_t sb = smem_u32(sm);
    const uint32_t Qh_s = sb, Ql_s = sb + Q_TILEB;
    const uint32_t KV_s = sb + 2 * Q_TILEB;      // Kh, Kl, Vh, Vl contiguous
    const uint32_t Kh_s = KV_s;
    const uint32_t Vh_s = KV_s + 2 * KV_TILEB;

    const int qt = blockIdx.x, h = blockIdx.y, b = blockIdx.z;
    const int tid = threadIdx.x, lane = tid & 31, wid = tid >> 5;
    const float cscale = rsqrtf((float)HDIM) * 1.44269504f;   // attn_scale * log2(e)

    const size_t qtok = (size_t)b * SEQ + (size_t)qt * 128;
    const size_t hoff = (size_t)h * HDIM;

    // ---- load Q tile (hi/lo) once: 2 arrays x 128 rows x 20 chunks ----
#pragma unroll
    for (int i = 0; i < 20; i++) {
        int idx = i * 256 + tid;
        int arr = idx / 2560;
        int rem = idx - arr * 2560;
        int r = rem / 20, c = rem - r * 20;
        const __nv_bfloat16* g = (arr ? g_Ql : g_Qh) + (qtok + r) * DD + hoff + c * 8;
        cp16(sb + arr * Q_TILEB + r * AQ_ROWB + c * 16, g);
    }
    CP_COMMIT();

    // per-lane state: rows r0 = wid*16 + (lane>>2), r1 = r0+8
    float m0 = -1e30f, m1 = -1e30f, l0 = 0.f, l1 = 0.f;
    float oacc[20][4];
#pragma unroll
    for (int v = 0; v < 20; v++)
#pragma unroll
        for (int j = 0; j < 4; j++) oacc[v][j] = 0.f;

    // fragment address precompute
    const uint32_t qa_off = (uint32_t)((wid * 16 + (lane & 15)) * AQ_ROWB + (lane >> 4) * 16);
    const uint32_t kb_lane = (uint32_t)((((lane >> 4) & 1) * 8 + (lane & 7)) * AQ_ROWB + ((lane >> 3) & 1) * 16);
    const uint32_t v_lane = (uint32_t)((lane & 15) * AQ_ROWB + (lane >> 4) * 16);

    for (int kt = 0; kt < SEQ / 64; kt++) {
        // ---- load K/V tile (hi/lo): 4 arrays x 64 rows x 20 chunks ----
        const size_t ktok = (size_t)b * SEQ + (size_t)kt * 64;
        {
            const __nv_bfloat16* gs[4] = {g_Kh, g_Kl, g_Vh, g_Vl};
#pragma unroll
            for (int i = 0; i < 20; i++) {
                int idx = i * 256 + tid;
                int arr = idx / 1280;
                int rem = idx - arr * 1280;
                int r = rem / 20, c = rem - r * 20;
                cp16(KV_s + arr * KV_TILEB + r * AQ_ROWB + c * 16,
                     gs[arr] + (ktok + r) * DD + hoff + c * 8);
            }
            CP_COMMIT();
            CP_WAIT(0);
        }
        __syncthreads();

        // ---- S = Q K^T : per warp 16x64, 3 passes ----
        float sacc[8][4];
#pragma unroll
        for (int nt = 0; nt < 8; nt++)
#pragma unroll
            for (int j = 0; j < 4; j++) sacc[nt][j] = 0.f;

#pragma unroll
        for (int k = 0; k < 10; k++) {
            uint32_t ah[4], al[4];
            ldsm4(ah, Qh_s + qa_off + k * 32);
            ldsm4(al, Ql_s + qa_off + k * 32);
#pragma unroll
            for (int np = 0; np < 4; np++) {
                uint32_t bh[4], bl[4];
                uint32_t kaddr = Kh_s + (uint32_t)(np * 16 * AQ_ROWB) + kb_lane + k * 32;
                ldsm4(bh, kaddr);
                ldsm4(bl, kaddr + KV_TILEB);         // Kl = Kh + KV_TILEB
#pragma unroll
                for (int half = 0; half < 2; half++) {
                    float* d = sacc[np * 2 + half];
                    mma16816(d, ah, bh + half * 2);
                    mma16816(d, ah, bl + half * 2);
                    mma16816(d, al, bh + half * 2);
                }
            }
        }

        // ---- online softmax (scaled into log2 domain) ----
        float mx0 = -1e30f, mx1 = -1e30f;
#pragma unroll
        for (int nt = 0; nt < 8; nt++) {
            sacc[nt][0] *= cscale; sacc[nt][1] *= cscale;
            sacc[nt][2] *= cscale; sacc[nt][3] *= cscale;
            mx0 = fmaxf(mx0, fmaxf(sacc[nt][0], sacc[nt][1]));
            mx1 = fmaxf(mx1, fmaxf(sacc[nt][2], sacc[nt][3]));
        }
        mx0 = fmaxf(mx0, __shfl_xor_sync(0xffffffffu, mx0, 1));
        mx0 = fmaxf(mx0, __shfl_xor_sync(0xffffffffu, mx0, 2));
        mx1 = fmaxf(mx1, __shfl_xor_sync(0xffffffffu, mx1, 1));
        mx1 = fmaxf(mx1, __shfl_xor_sync(0xffffffffu, mx1, 2));
        float nm0 = fmaxf(m0, mx0), nm1 = fmaxf(m1, mx1);
        float al0 = ex2f(m0 - nm0), al1 = ex2f(m1 - nm1);
        m0 = nm0; m1 = nm1;

        float ps0 = 0.f, ps1 = 0.f;
#pragma unroll
        for (int nt = 0; nt < 8; nt++) {
            sacc[nt][0] = ex2f(sacc[nt][0] - nm0);
            sacc[nt][1] = ex2f(sacc[nt][1] - nm0);
            sacc[nt][2] = ex2f(sacc[nt][2] - nm1);
            sacc[nt][3] = ex2f(sacc[nt][3] - nm1);
            ps0 += sacc[nt][0] + sacc[nt][1];
            ps1 += sacc[nt][2] + sacc[nt][3];
        }
        ps0 += __shfl_xor_sync(0xffffffffu, ps0, 1);
        ps0 += __shfl_xor_sync(0xffffffffu, ps0, 2);
        ps1 += __shfl_xor_sync(0xffffffffu, ps1, 1);
        ps1 += __shfl_xor_sync(0xffffffffu, ps1, 2);
        l0 = l0 * al0 + ps0;
        l1 = l1 * al1 + ps1;

#pragma unroll
        for (int v = 0; v < 20; v++) {
            oacc[v][0] *= al0; oacc[v][1] *= al0;
            oacc[v][2] *= al1; oacc[v][3] *= al1;
        }

        // ---- O += P V : P repacked from sacc, V via ldmatrix.trans ----
#pragma unroll
        for (int kt2 = 0; kt2 < 4; kt2++) {
            const float* p0 = sacc[2 * kt2];
            const float* p1 = sacc[2 * kt2 + 1];
            uint32_t pah[4], pal[4];
            pah[0] = pack2(p0[0], p0[1]); pal[0] = pack2(res_lo(p0[0]), res_lo(p0[1]));
            pah[1] = pack2(p0[2], p0[3]); pal[1] = pack2(res_lo(p0[2]), res_lo(p0[3]));
            pah[2] = pack2(p1[0], p1[1]); pal[2] = pack2(res_lo(p1[0]), res_lo(p1[1]));
            pah[3] = pack2(p1[2], p1[3]); pal[3] = pack2(res_lo(p1[2]), res_lo(p1[3]));
#pragma unroll
            for (int vp = 0; vp < 10; vp++) {
                uint32_t bvh[4], bvl[4];
                uint32_t vaddr = Vh_s + (uint32_t)(kt2 * 16 * AQ_ROWB) + v_lane + vp * 32;
                ldsm4t(bvh, vaddr);
                ldsm4t(bvl, vaddr + KV_TILEB);       // Vl = Vh + KV_TILEB (FIXED)
#pragma unroll
                for (int half = 0; half < 2; half++) {
                    float* d = oacc[vp * 2 + half];
                    mma16816(d, pah, bvh + half * 2);
                    mma16816(d, pah, bvl + half * 2);
                    mma16816(d, pal, bvh + half * 2);
                }
            }
        }
        __syncthreads();
    }

    // ---- epilogue: normalize, split hi/lo, store bf16 ----
    float inv0 = 1.f / l0, inv1 = 1.f / l1;
    const size_t tok0 = qtok + wid * 16 + (lane >> 2);
    const size_t tok1 = tok0 + 8;
#pragma unroll
    for (int nt = 0; nt < 20; nt++) {
        size_t col = hoff + nt * 8 + (lane & 3) * 2;
        float f0 = oacc[nt][0] * inv0, f1 = oacc[nt][1] * inv0;
        float f2 = oacc[nt][2] * inv1, f3 = oacc[nt][3] * inv1;
        *reinterpret_cast<uint32_t*>(g_AOh + tok0 * DD + col) = pack2(f0, f1);
        *reinterpret_cast<uint32_t*>(g_AOl + tok0 * DD + col) = pack2(res_lo(f0), res_lo(f1));
        *reinterpret_cast<uint32_t*>(g_AOh + tok1 * DD + col) = pack2(f2, f3);
        *reinterpret_cast<uint32_t*>(g_AOl + tok1 * DD + col) = pack2(res_lo(f2), res_lo(f3));
    }
}

// ============================================================
// host launcher
// ============================================================
extern "C" void kernel_launch(void* const* d_in, const int* in_sizes, int n_in,
                              void* d_out, int out_size)
{
    const float* x   = (const float*)d_in[0];
    const float* pal = (const float*)d_in[1];
    const float* Wq  = (const float*)d_in[2];
    const float* Wk  = (const float*)d_in[3];
    const float* Wv  = (const float*)d_in[4];
    const float* Wo  = (const float*)d_in[5];
    const float* bo  = (const float*)d_in[6];
    const float* qd  = (const float*)d_in[7];
    const float* qu  = (const float*)d_in[8];
    const float* kd  = (const float*)d_in[9];
    const float* ku  = (const float*)d_in[10];
    const float* vd  = (const float*)d_in[11];
    const float* vu  = (const float*)d_in[12];
    const float* od  = (const float*)d_in[13];
    const float* ou  = (const float*)d_in[14];
    float* out = (float*)d_out;

    __nv_bfloat16 *pWhi, *pWlo, *pAhi, *pAlo;
    __nv_bfloat16 *pQh, *pQl, *pKh, *pKl, *pVh, *pVl, *pAOh, *pAOl;
    cudaGetSymbolAddress((void**)&pWhi, g_Whi);
    cudaGetSymbolAddress((void**)&pWlo, g_Wlo);
    cudaGetSymbolAddress((void**)&pAhi, g_Ahi);
    cudaGetSymbolAddress((void**)&pAlo, g_Alo);
    cudaGetSymbolAddress((void**)&pQh, g_Qh);
    cudaGetSymbolAddress((void**)&pQl, g_Ql);
    cudaGetSymbolAddress((void**)&pKh, g_Kh);
    cudaGetSymbolAddress((void**)&pKl, g_Kl);
    cudaGetSymbolAddress((void**)&pVh, g_Vh);
    cudaGetSymbolAddress((void**)&pVl, g_Vl);
    cudaGetSymbolAddress((void**)&pAOh, g_AOh);
    cudaGetSymbolAddress((void**)&pAOl, g_AOl);

    cudaFuncSetAttribute(gemm_tc, cudaFuncAttributeMaxDynamicSharedMemorySize, GEMM_SMEM);
    cudaFuncSetAttribute(attn_tc, cudaFuncAttributeMaxDynamicSharedMemorySize, ATTN_SMEM);

    const size_t WSZ = (size_t)DD * DD;

    // 0) palette contractions
    k_downup<<<(8 * RK * DD + 255) / 256, 256>>>(pal, qd, qu, kd, ku, vd, vu, od, ou);
    // 1) effective weights (LoRA folded) -> bf16 hi/lo
    k_weff<<<(4 * DD * DD / 4 + 255) / 256, 256>>>(Wq, Wk, Wv, Wo);
    // 1b) x -> bf16 hi/lo
    k_cvtA<<<(NTOK * DD / 4 + 255) / 256, 256>>>(x);
    // 2) Q,K,V projections -> bf16 hi/lo directly
    dim3 gg(DD / 128, NTOK / 128);
    gemm_tc<<<gg, 256, GEMM_SMEM>>>(pAhi, pAlo, pWhi + 0 * WSZ, pWlo + 0 * WSZ, nullptr, nullptr, pQh, pQl);
    gemm_tc<<<gg, 256, GEMM_SMEM>>>(pAhi, pAlo, pWhi + 1 * WSZ, pWlo + 1 * WSZ, nullptr, nullptr, pKh, pKl);
    gemm_tc<<<gg, 256, GEMM_SMEM>>>(pAhi, pAlo, pWhi + 2 * WSZ, pWlo + 2 * WSZ, nullptr, nullptr, pVh, pVl);
    // 3) attention (tensor cores) -> bf16 hi/lo AO
    dim3 gattn(SEQ / 128, NH, NB);
    attn_tc<<<gattn, 256, ATTN_SMEM>>>();
    // 4) output projection + bias -> fp32 out
    gemm_tc<<<gg, 256, GEMM_SMEM>>>(pAOh, pAOl, pWhi + 3 * WSZ, pWlo + 3 * WSZ, bo, out, nullptr, nullptr);
}

// round 10
// speedup vs baseline: 4.2428x; 1.1054x over previous
#include <cuda_runtime.h>
#include <cuda_bf16.h>
#include <math.h>
#include <cstdint>

#define DD 1280
#define NH 8
#define HDIM 160
#define RK 4
#define NB 2
#define SEQ 2048
#define NTOK (NB*SEQ)

// ---- scratch (static __device__ arrays; no allocation) ----
__device__ float g_down[4][RK*DD];
__device__ float g_up[4][RK*DD];
__device__ __nv_bfloat16 g_Whi[4][DD*DD];
__device__ __nv_bfloat16 g_Wlo[4][DD*DD];
__device__ __nv_bfloat16 g_Ahi[NTOK*DD];
__device__ __nv_bfloat16 g_Alo[NTOK*DD];
__device__ __nv_bfloat16 g_Qh[NTOK*DD];
__device__ __nv_bfloat16 g_Ql[NTOK*DD];
__device__ __nv_bfloat16 g_Kh[NTOK*DD];
__device__ __nv_bfloat16 g_Kl[NTOK*DD];
__device__ __nv_bfloat16 g_Vh[NTOK*DD];
__device__ __nv_bfloat16 g_Vl[NTOK*DD];
__device__ __nv_bfloat16 g_AOh[NTOK*DD];
__device__ __nv_bfloat16 g_AOl[NTOK*DD];

// ============================================================
// helpers (family-portable, sm_80+)
// ============================================================
__device__ __forceinline__ uint32_t smem_u32(const void* p) {
    uint32_t a;
    asm("{ .reg .u64 t; cvta.to.shared.u64 t, %1; cvt.u32.u64 %0, t; }" : "=r"(a) : "l"(p));
    return a;
}
__device__ __forceinline__ void cp16(uint32_t dst, const void* src) {
    asm volatile("cp.async.cg.shared.global [%0], [%1], 16;" :: "r"(dst), "l"(src) : "memory");
}
#define CP_COMMIT() asm volatile("cp.async.commit_group;" ::: "memory")
#define CP_WAIT(n)  asm volatile("cp.async.wait_group %0;" :: "n"(n) : "memory")

__device__ __forceinline__ void ldsm4(uint32_t* r, uint32_t addr) {
    asm volatile("ldmatrix.sync.aligned.m8n8.x4.shared.b16 {%0,%1,%2,%3}, [%4];"
        : "=r"(r[0]), "=r"(r[1]), "=r"(r[2]), "=r"(r[3]) : "r"(addr));
}
__device__ __forceinline__ void ldsm4t(uint32_t* r, uint32_t addr) {
    asm volatile("ldmatrix.sync.aligned.m8n8.x4.trans.shared.b16 {%0,%1,%2,%3}, [%4];"
        : "=r"(r[0]), "=r"(r[1]), "=r"(r[2]), "=r"(r[3]) : "r"(addr));
}
__device__ __forceinline__ void mma16816(float* d, const uint32_t* a, const uint32_t* b) {
    asm volatile(
        "mma.sync.aligned.m16n8k16.row.col.f32.bf16.bf16.f32 "
        "{%0,%1,%2,%3}, {%4,%5,%6,%7}, {%8,%9}, {%0,%1,%2,%3};"
        : "+f"(d[0]), "+f"(d[1]), "+f"(d[2]), "+f"(d[3])
        : "r"(a[0]), "r"(a[1]), "r"(a[2]), "r"(a[3]), "r"(b[0]), "r"(b[1]));
}
__device__ __forceinline__ float ex2f(float x) {
    float y; asm("ex2.approx.f32 %0, %1;" : "=f"(y) : "f"(x)); return y;
}
__device__ __forceinline__ uint32_t pack2(float a, float b) {
    __nv_bfloat162 v = __floats2bfloat162_rn(a, b);
    return reinterpret_cast<uint32_t&>(v);
}
__device__ __forceinline__ float res_lo(float f) {
    return f - __bfloat162float(__float2bfloat16(f));
}

// ============================================================
// Kernel 0: contract palette into down/up vectors for 4 LoRAs
// ============================================================
__global__ void k_downup(const float* __restrict__ pal,
    const float* __restrict__ qd, const float* __restrict__ qu,
    const float* __restrict__ kd, const float* __restrict__ ku,
    const float* __restrict__ vd, const float* __restrict__ vu,
    const float* __restrict__ od, const float* __restrict__ ou)
{
    __shared__ float p[15];
    if (threadIdx.x < 15) p[threadIdx.x] = pal[threadIdx.x];
    __syncthreads();
    int idx = blockIdx.x * blockDim.x + threadIdx.x;
    if (idx >= 8 * RK * DD) return;
    int which = idx / (RK * DD);
    int e = idx - which * (RK * DD);
    const float* srcs[8] = {qd, qu, kd, ku, vd, vu, od, ou};
    const float* s = srcs[which];
    float acc = 0.f;
#pragma unroll
    for (int j = 0; j < 15; j++) acc += p[j] * s[e * 15 + j];
    if (which & 1) g_up[which >> 1][e] = acc;
    else          g_down[which >> 1][e] = acc;
}

// ============================================================
// Kernel 1: W_eff = W + up @ down, written as bf16 hi/lo pair
// ============================================================
__global__ void k_weff(const float* __restrict__ Wq, const float* __restrict__ Wk,
                       const float* __restrict__ Wv, const float* __restrict__ Wo)
{
    const int per_w = DD * DD / 4;
    int idx = blockIdx.x * blockDim.x + threadIdx.x;
    if (idx >= 4 * per_w) return;
    int w = idx / per_w;
    int e4 = idx - w * per_w;
    int o = e4 / (DD / 4);
    int i4 = e4 - o * (DD / 4);
    const float* Ws[4] = {Wq, Wk, Wv, Wo};
    float4 acc = reinterpret_cast<const float4*>(Ws[w])[e4];
#pragma unroll
    for (int r = 0; r < RK; r++) {
        float u = g_up[w][o * RK + r];
        float4 d = reinterpret_cast<const float4*>(&g_down[w][r * DD])[i4];
        acc.x += u * d.x; acc.y += u * d.y; acc.z += u * d.z; acc.w += u * d.w;
    }
    float v[4] = {acc.x, acc.y, acc.z, acc.w};
    reinterpret_cast<uint32_t*>(&g_Whi[w][0])[2*e4]   = pack2(v[0], v[1]);
    reinterpret_cast<uint32_t*>(&g_Whi[w][0])[2*e4+1] = pack2(v[2], v[3]);
    reinterpret_cast<uint32_t*>(&g_Wlo[w][0])[2*e4]   = pack2(res_lo(v[0]), res_lo(v[1]));
    reinterpret_cast<uint32_t*>(&g_Wlo[w][0])[2*e4+1] = pack2(res_lo(v[2]), res_lo(v[3]));
}

// ============================================================
// Kernel 1b: fp32 activation -> bf16 hi/lo pair (input x only)
// ============================================================
__global__ void k_cvtA(const float* __restrict__ src)
{
    int i = blockIdx.x * blockDim.x + threadIdx.x;
    if (i >= NTOK * DD / 4) return;
    float4 a = reinterpret_cast<const float4*>(src)[i];
    float v[4] = {a.x, a.y, a.z, a.w};
    reinterpret_cast<uint32_t*>(g_Ahi)[2*i]   = pack2(v[0], v[1]);
    reinterpret_cast<uint32_t*>(g_Ahi)[2*i+1] = pack2(v[2], v[3]);
    reinterpret_cast<uint32_t*>(g_Alo)[2*i]   = pack2(res_lo(v[0]), res_lo(v[1]));
    reinterpret_cast<uint32_t*>(g_Alo)[2*i+1] = pack2(res_lo(v[2]), res_lo(v[3]));
}

// ============================================================
// GEMM core (device inline): 128x128 tile, BK=32, 8 warps,
// 3-pass split bf16. Caller provides pointers + epilogue mode.
// ============================================================
#define BK 32
#define TSTRIDE 80
#define TILEB (128 * TSTRIDE)
#define STAGEB (4 * TILEB)
#define GEMM_SMEM (2 * STAGEB)
#define NCHUNK (DD / BK)

struct GemmOut {
    float* Cf; const float* bias;
    __nv_bfloat16* Ch; __nv_bfloat16* Cl;
};

__device__ __forceinline__ void gemm_body(
    const __nv_bfloat16* __restrict__ Ahi, const __nv_bfloat16* __restrict__ Alo,
    const __nv_bfloat16* __restrict__ Whi, const __nv_bfloat16* __restrict__ Wlo,
    const GemmOut& o, size_t tileM, size_t tileN, char* smem)
{
    const uint32_t sbase = smem_u32(smem);
    const int tid = threadIdx.x;
    const int lane = tid & 31, wid = tid >> 5;
    const int warp_m = (wid & 3) * 32, warp_n = (wid >> 2) * 64;
    const int K = DD, N = DD;

    const __nv_bfloat16* srcs[4] = {Ahi, Alo, Whi, Wlo};

    auto load_stage = [&](int kc, int s) {
        const int kcol = kc * BK;
        uint32_t dst0 = sbase + s * STAGEB;
#pragma unroll
        for (int i = 0; i < 8; i++) {
            int idx = i * 256 + tid;
            int t = idx >> 9;
            int rem = idx & 511;
            int r = rem >> 2, c = rem & 3;
            size_t grow = (t < 2) ? (tileM + r) : (tileN + r);
            const __nv_bfloat16* src = srcs[t] + grow * K + kcol + c * 8;
            cp16(dst0 + t * TILEB + r * TSTRIDE + c * 16, src);
        }
        CP_COMMIT();
    };

    float acc[2][8][4];
#pragma unroll
    for (int mf = 0; mf < 2; mf++)
#pragma unroll
        for (int nf = 0; nf < 8; nf++)
#pragma unroll
            for (int j = 0; j < 4; j++) acc[mf][nf][j] = 0.f;

    load_stage(0, 0);

    const int a_row = warp_m + ((lane >> 3) & 1) * 8 + (lane & 7);
    const uint32_t a_off = (uint32_t)(a_row * TSTRIDE + (lane >> 4) * 16);
    const int b_row = warp_n + ((lane >> 4) & 1) * 8 + (lane & 7);
    const uint32_t b_off = (uint32_t)(b_row * TSTRIDE + ((lane >> 3) & 1) * 16);

    for (int kc = 0; kc < NCHUNK; kc++) {
        const int s = kc & 1;
        if (kc + 1 < NCHUNK) { load_stage(kc + 1, s ^ 1); CP_WAIT(1); }
        else { CP_WAIT(0); }
        __syncthreads();

        const uint32_t stage = sbase + s * STAGEB;
#pragma unroll
        for (int ks = 0; ks < 2; ks++) {
            const uint32_t kb = ks * 32;
            uint32_t ah[2][4], al[2][4];
#pragma unroll
            for (int mf = 0; mf < 2; mf++) {
                ldsm4(ah[mf], stage + a_off + mf * (16 * TSTRIDE) + kb);
                ldsm4(al[mf], stage + TILEB + a_off + mf * (16 * TSTRIDE) + kb);
            }
#pragma unroll
            for (int np = 0; np < 4; np++) {
                uint32_t bh[4], bl[4];
                ldsm4(bh, stage + 2 * TILEB + b_off + np * (16 * TSTRIDE) + kb);
                ldsm4(bl, stage + 3 * TILEB + b_off + np * (16 * TSTRIDE) + kb);
#pragma unroll
                for (int mf = 0; mf < 2; mf++) {
#pragma unroll
                    for (int half = 0; half < 2; half++) {
                        float* d = acc[mf][np * 2 + half];
                        mma16816(d, ah[mf], bh + half * 2);
                        mma16816(d, ah[mf], bl + half * 2);
                        mma16816(d, al[mf], bh + half * 2);
                    }
                }
            }
        }
        __syncthreads();
    }

    const int er = lane >> 2;
    const int ec = (lane & 3) * 2;
#pragma unroll
    for (int mf = 0; mf < 2; mf++) {
        size_t row0 = tileM + warp_m + mf * 16 + er;
#pragma unroll
        for (int nf = 0; nf < 8; nf++) {
            size_t col = tileN + warp_n + nf * 8 + ec;
            float f0 = acc[mf][nf][0], f1 = acc[mf][nf][1];
            float f2 = acc[mf][nf][2], f3 = acc[mf][nf][3];
            if (o.Cf) {
                float bx = 0.f, by = 0.f;
                if (o.bias) { bx = o.bias[col]; by = o.bias[col + 1]; }
                float2 v0 = {f0 + bx, f1 + by};
                float2 v1 = {f2 + bx, f3 + by};
                *reinterpret_cast<float2*>(o.Cf + row0 * N + col) = v0;
                *reinterpret_cast<float2*>(o.Cf + (row0 + 8) * N + col) = v1;
            } else {
                *reinterpret_cast<uint32_t*>(o.Ch + row0 * N + col)       = pack2(f0, f1);
                *reinterpret_cast<uint32_t*>(o.Cl + row0 * N + col)       = pack2(res_lo(f0), res_lo(f1));
                *reinterpret_cast<uint32_t*>(o.Ch + (row0 + 8) * N + col) = pack2(f2, f3);
                *reinterpret_cast<uint32_t*>(o.Cl + (row0 + 8) * N + col) = pack2(res_lo(f2), res_lo(f3));
            }
        }
    }
}

// ---- fused QKV: grid (N/128, M/128, 3); z selects weight/output ----
__global__ void __launch_bounds__(256, 2) qkv_tc()
{
    extern __shared__ char smem[];
    const int z = blockIdx.z;
    GemmOut o;
    o.Cf = nullptr; o.bias = nullptr;
    o.Ch = (z == 0) ? g_Qh : (z == 1) ? g_Kh : g_Vh;
    o.Cl = (z == 0) ? g_Ql : (z == 1) ? g_Kl : g_Vl;
    gemm_body(g_Ahi, g_Alo, g_Whi[z], g_Wlo[z],
              o, (size_t)blockIdx.y * 128, (size_t)blockIdx.x * 128, smem);
}

// ---- AO projection: fp32 out + bias ----
__global__ void __launch_bounds__(256, 2) o_tc(const float* __restrict__ bias,
                                               float* __restrict__ out)
{
    extern __shared__ char smem[];
    GemmOut o;
    o.Cf = out; o.bias = bias; o.Ch = nullptr; o.Cl = nullptr;
    gemm_body(g_AOh, g_AOl, g_Whi[3], g_Wlo[3],
              o, (size_t)blockIdx.y * 128, (size_t)blockIdx.x * 128, smem);
}

// ============================================================
// Kernel 3: flash attention on tensor cores (split-bf16, FA2)
// BQ=128, BK=64, hd=160. 8 warps x 16 rows. grid (16, 8, 2).
// ============================================================
#define AQ_STR 168                 // elems; 336 B row stride
#define AQ_ROWB (AQ_STR * 2)       // 336
#define Q_TILEB (128 * AQ_ROWB)    // 43008
#define KV_TILEB (64 * AQ_ROWB)    // 21504
#define ATTN_SMEM (2 * Q_TILEB + 4 * KV_TILEB)   // 172032

__global__ void __launch_bounds__(256) attn_tc()
{
    extern __shared__ char sm[];
    const uint32_t sb = smem_u32(sm);
    const uint32_t Qh_s = sb, Ql_s = sb + Q_TILEB;
    const uint32_t KV_s = sb + 2 * Q_TILEB;      // Kh, Kl, Vh, Vl contiguous
    const uint32_t Kh_s = KV_s;
    const uint32_t Vh_s = KV_s + 2 * KV_TILEB;

    const int qt = blockIdx.x, h = blockIdx.y, b = blockIdx.z;
    const int tid = threadIdx.x, lane = tid & 31, wid = tid >> 5;
    const float cscale = rsqrtf((float)HDIM) * 1.44269504f;   // attn_scale * log2(e)

    const size_t qtok = (size_t)b * SEQ + (size_t)qt * 128;
    const size_t hoff = (size_t)h * HDIM;

    // ---- load Q tile (hi/lo) once ----
#pragma unroll
    for (int i = 0; i < 20; i++) {
        int idx = i * 256 + tid;
        int arr = idx / 2560;
        int rem = idx - arr * 2560;
        int r = rem / 20, c = rem - r * 20;
        const __nv_bfloat16* g = (arr ? g_Ql : g_Qh) + (qtok + r) * DD + hoff + c * 8;
        cp16(sb + arr * Q_TILEB + r * AQ_ROWB + c * 16, g);
    }
    CP_COMMIT();

    float m0 = -1e30f, m1 = -1e30f, l0 = 0.f, l1 = 0.f;
    float oacc[20][4];
#pragma unroll
    for (int v = 0; v < 20; v++)
#pragma unroll
        for (int j = 0; j < 4; j++) oacc[v][j] = 0.f;

    const uint32_t qa_off = (uint32_t)((wid * 16 + (lane & 15)) * AQ_ROWB + (lane >> 4) * 16);
    const uint32_t kb_lane = (uint32_t)((((lane >> 4) & 1) * 8 + (lane & 7)) * AQ_ROWB + ((lane >> 3) & 1) * 16);
    const uint32_t v_lane = (uint32_t)((lane & 15) * AQ_ROWB + (lane >> 4) * 16);

    for (int kt = 0; kt < SEQ / 64; kt++) {
        const size_t ktok = (size_t)b * SEQ + (size_t)kt * 64;
        {
            const __nv_bfloat16* gs[4] = {g_Kh, g_Kl, g_Vh, g_Vl};
#pragma unroll
            for (int i = 0; i < 20; i++) {
                int idx = i * 256 + tid;
                int arr = idx / 1280;
                int rem = idx - arr * 1280;
                int r = rem / 20, c = rem - r * 20;
                cp16(KV_s + arr * KV_TILEB + r * AQ_ROWB + c * 16,
                     gs[arr] + (ktok + r) * DD + hoff + c * 8);
            }
            CP_COMMIT();
            CP_WAIT(0);
        }
        __syncthreads();

        // ---- S = Q K^T ----
        float sacc[8][4];
#pragma unroll
        for (int nt = 0; nt < 8; nt++)
#pragma unroll
            for (int j = 0; j < 4; j++) sacc[nt][j] = 0.f;

#pragma unroll
        for (int k = 0; k < 10; k++) {
            uint32_t ah[4], al[4];
            ldsm4(ah, Qh_s + qa_off + k * 32);
            ldsm4(al, Ql_s + qa_off + k * 32);
#pragma unroll
            for (int np = 0; np < 4; np++) {
                uint32_t bh[4], bl[4];
                uint32_t kaddr = Kh_s + (uint32_t)(np * 16 * AQ_ROWB) + kb_lane + k * 32;
                ldsm4(bh, kaddr);
                ldsm4(bl, kaddr + KV_TILEB);
#pragma unroll
                for (int half = 0; half < 2; half++) {
                    float* d = sacc[np * 2 + half];
                    mma16816(d, ah, bh + half * 2);
                    mma16816(d, ah, bl + half * 2);
                    mma16816(d, al, bh + half * 2);
                }
            }
        }

        // ---- online softmax ----
        float mx0 = -1e30f, mx1 = -1e30f;
#pragma unroll
        for (int nt = 0; nt < 8; nt++) {
            sacc[nt][0] *= cscale; sacc[nt][1] *= cscale;
            sacc[nt][2] *= cscale; sacc[nt][3] *= cscale;
            mx0 = fmaxf(mx0, fmaxf(sacc[nt][0], sacc[nt][1]));
            mx1 = fmaxf(mx1, fmaxf(sacc[nt][2], sacc[nt][3]));
        }
        mx0 = fmaxf(mx0, __shfl_xor_sync(0xffffffffu, mx0, 1));
        mx0 = fmaxf(mx0, __shfl_xor_sync(0xffffffffu, mx0, 2));
        mx1 = fmaxf(mx1, __shfl_xor_sync(0xffffffffu, mx1, 1));
        mx1 = fmaxf(mx1, __shfl_xor_sync(0xffffffffu, mx1, 2));
        float nm0 = fmaxf(m0, mx0), nm1 = fmaxf(m1, mx1);
        float al0 = ex2f(m0 - nm0), al1 = ex2f(m1 - nm1);
        m0 = nm0; m1 = nm1;

        float ps0 = 0.f, ps1 = 0.f;
#pragma unroll
        for (int nt = 0; nt < 8; nt++) {
            sacc[nt][0] = ex2f(sacc[nt][0] - nm0);
            sacc[nt][1] = ex2f(sacc[nt][1] - nm0);
            sacc[nt][2] = ex2f(sacc[nt][2] - nm1);
            sacc[nt][3] = ex2f(sacc[nt][3] - nm1);
            ps0 += sacc[nt][0] + sacc[nt][1];
            ps1 += sacc[nt][2] + sacc[nt][3];
        }
        ps0 += __shfl_xor_sync(0xffffffffu, ps0, 1);
        ps0 += __shfl_xor_sync(0xffffffffu, ps0, 2);
        ps1 += __shfl_xor_sync(0xffffffffu, ps1, 1);
        ps1 += __shfl_xor_sync(0xffffffffu, ps1, 2);
        l0 = l0 * al0 + ps0;
        l1 = l1 * al1 + ps1;

#pragma unroll
        for (int v = 0; v < 20; v++) {
            oacc[v][0] *= al0; oacc[v][1] *= al0;
            oacc[v][2] *= al1; oacc[v][3] *= al1;
        }

        // ---- O += P V ----
#pragma unroll
        for (int kt2 = 0; kt2 < 4; kt2++) {
            const float* p0 = sacc[2 * kt2];
            const float* p1 = sacc[2 * kt2 + 1];
            uint32_t pah[4], pal[4];
            pah[0] = pack2(p0[0], p0[1]); pal[0] = pack2(res_lo(p0[0]), res_lo(p0[1]));
            pah[1] = pack2(p0[2], p0[3]); pal[1] = pack2(res_lo(p0[2]), res_lo(p0[3]));
            pah[2] = pack2(p1[0], p1[1]); pal[2] = pack2(res_lo(p1[0]), res_lo(p1[1]));
            pah[3] = pack2(p1[2], p1[3]); pal[3] = pack2(res_lo(p1[2]), res_lo(p1[3]));
#pragma unroll
            for (int vp = 0; vp < 10; vp++) {
                uint32_t bvh[4], bvl[4];
                uint32_t vaddr = Vh_s + (uint32_t)(kt2 * 16 * AQ_ROWB) + v_lane + vp * 32;
                ldsm4t(bvh, vaddr);
                ldsm4t(bvl, vaddr + KV_TILEB);
#pragma unroll
                for (int half = 0; half < 2; half++) {
                    float* d = oacc[vp * 2 + half];
                    mma16816(d, pah, bvh + half * 2);
                    mma16816(d, pah, bvl + half * 2);
                    mma16816(d, pal, bvh + half * 2);
                }
            }
        }
        __syncthreads();
    }

    // ---- epilogue ----
    float inv0 = 1.f / l0, inv1 = 1.f / l1;
    const size_t tok0 = qtok + wid * 16 + (lane >> 2);
    const size_t tok1 = tok0 + 8;
#pragma unroll
    for (int nt = 0; nt < 20; nt++) {
        size_t col = hoff + nt * 8 + (lane & 3) * 2;
        float f0 = oacc[nt][0] * inv0, f1 = oacc[nt][1] * inv0;
        float f2 = oacc[nt][2] * inv1, f3 = oacc[nt][3] * inv1;
        *reinterpret_cast<uint32_t*>(g_AOh + tok0 * DD + col) = pack2(f0, f1);
        *reinterpret_cast<uint32_t*>(g_AOl + tok0 * DD + col) = pack2(res_lo(f0), res_lo(f1));
        *reinterpret_cast<uint32_t*>(g_AOh + tok1 * DD + col) = pack2(f2, f3);
        *reinterpret_cast<uint32_t*>(g_AOl + tok1 * DD + col) = pack2(res_lo(f2), res_lo(f3));
    }
}

// ============================================================
// host launcher
// ============================================================
extern "C" void kernel_launch(void* const* d_in, const int* in_sizes, int n_in,
                              void* d_out, int out_size)
{
    const float* x   = (const float*)d_in[0];
    const float* pal = (const float*)d_in[1];
    const float* Wq  = (const float*)d_in[2];
    const float* Wk  = (const float*)d_in[3];
    const float* Wv  = (const float*)d_in[4];
    const float* Wo  = (const float*)d_in[5];
    const float* bo  = (const float*)d_in[6];
    const float* qd  = (const float*)d_in[7];
    const float* qu  = (const float*)d_in[8];
    const float* kd  = (const float*)d_in[9];
    const float* ku  = (const float*)d_in[10];
    const float* vd  = (const float*)d_in[11];
    const float* vu  = (const float*)d_in[12];
    const float* od  = (const float*)d_in[13];
    const float* ou  = (const float*)d_in[14];
    float* out = (float*)d_out;

    cudaFuncSetAttribute(qkv_tc, cudaFuncAttributeMaxDynamicSharedMemorySize, GEMM_SMEM);
    cudaFuncSetAttribute(o_tc, cudaFuncAttributeMaxDynamicSharedMemorySize, GEMM_SMEM);
    cudaFuncSetAttribute(attn_tc, cudaFuncAttributeMaxDynamicSharedMemorySize, ATTN_SMEM);

    // 0) palette contractions
    k_downup<<<(8 * RK * DD + 255) / 256, 256>>>(pal, qd, qu, kd, ku, vd, vu, od, ou);
    // 1) effective weights (LoRA folded) -> bf16 hi/lo
    k_weff<<<(4 * DD * DD / 4 + 255) / 256, 256>>>(Wq, Wk, Wv, Wo);
    // 1b) x -> bf16 hi/lo
    k_cvtA<<<(NTOK * DD / 4 + 255) / 256, 256>>>(x);
    // 2) fused Q,K,V projections -> bf16 hi/lo (one launch, 960 CTAs)
    dim3 gqkv(DD / 128, NTOK / 128, 3);
    qkv_tc<<<gqkv, 256, GEMM_SMEM>>>();
    // 3) attention (tensor cores) -> bf16 hi/lo AO
    dim3 gattn(SEQ / 128, NH, NB);
    attn_tc<<<gattn, 256, ATTN_SMEM>>>();
    // 4) output projection + bias -> fp32 out
    dim3 go(DD / 128, NTOK / 128);
    o_tc<<<go, 256, GEMM_SMEM>>>(bo, out);
}

// round 11
// speedup vs baseline: 5.8623x; 1.3817x over previous
#include <cuda_runtime.h>
#include <cuda_fp16.h>
#include <math.h>
#include <cstdint>

#define DD 1280
#define NH 8
#define HDIM 160
#define RK 4
#define NB 2
#define SEQ 2048
#define NTOK (NB*SEQ)

// ---- scratch (static __device__ arrays; no allocation) ----
__device__ float g_down[4][RK*DD];
__device__ float g_up[4][RK*DD];
__device__ __half g_Whi[4][DD*DD];
__device__ __half g_Wlo[4][DD*DD];
__device__ __half g_Ah[NTOK*DD];        // x, fp16 hi only
__device__ __half g_Qh[NTOK*DD];
__device__ __half g_Kh[NTOK*DD];
__device__ __half g_Kl[NTOK*DD];
__device__ __half g_Vh[NTOK*DD];
__device__ __half g_Vl[NTOK*DD];
__device__ __half g_AOh[NTOK*DD];

// ============================================================
// helpers (family-portable, sm_80+)
// ============================================================
__device__ __forceinline__ uint32_t smem_u32(const void* p) {
    uint32_t a;
    asm("{ .reg .u64 t; cvta.to.shared.u64 t, %1; cvt.u32.u64 %0, t; }" : "=r"(a) : "l"(p));
    return a;
}
__device__ __forceinline__ void cp16(uint32_t dst, const void* src) {
    asm volatile("cp.async.cg.shared.global [%0], [%1], 16;" :: "r"(dst), "l"(src) : "memory");
}
#define CP_COMMIT() asm volatile("cp.async.commit_group;" ::: "memory")
#define CP_WAIT(n)  asm volatile("cp.async.wait_group %0;" :: "n"(n) : "memory")

__device__ __forceinline__ void ldsm4(uint32_t* r, uint32_t addr) {
    asm volatile("ldmatrix.sync.aligned.m8n8.x4.shared.b16 {%0,%1,%2,%3}, [%4];"
        : "=r"(r[0]), "=r"(r[1]), "=r"(r[2]), "=r"(r[3]) : "r"(addr));
}
__device__ __forceinline__ void ldsm4t(uint32_t* r, uint32_t addr) {
    asm volatile("ldmatrix.sync.aligned.m8n8.x4.trans.shared.b16 {%0,%1,%2,%3}, [%4];"
        : "=r"(r[0]), "=r"(r[1]), "=r"(r[2]), "=r"(r[3]) : "r"(addr));
}
__device__ __forceinline__ void mma16816(float* d, const uint32_t* a, const uint32_t* b) {
    asm volatile(
        "mma.sync.aligned.m16n8k16.row.col.f32.f16.f16.f32 "
        "{%0,%1,%2,%3}, {%4,%5,%6,%7}, {%8,%9}, {%0,%1,%2,%3};"
        : "+f"(d[0]), "+f"(d[1]), "+f"(d[2]), "+f"(d[3])
        : "r"(a[0]), "r"(a[1]), "r"(a[2]), "r"(a[3]), "r"(b[0]), "r"(b[1]));
}
__device__ __forceinline__ float ex2f(float x) {
    float y; asm("ex2.approx.f32 %0, %1;" : "=f"(y) : "f"(x)); return y;
}
__device__ __forceinline__ uint32_t pack2(float a, float b) {
    __half2 v = __floats2half2_rn(a, b);
    return reinterpret_cast<uint32_t&>(v);
}
__device__ __forceinline__ float res_lo(float f) {
    return f - __half2float(__float2half_rn(f));
}

// ============================================================
// Kernel 0: contract palette into down/up vectors for 4 LoRAs
// ============================================================
__global__ void k_downup(const float* __restrict__ pal,
    const float* __restrict__ qd, const float* __restrict__ qu,
    const float* __restrict__ kd, const float* __restrict__ ku,
    const float* __restrict__ vd, const float* __restrict__ vu,
    const float* __restrict__ od, const float* __restrict__ ou)
{
    __shared__ float p[15];
    if (threadIdx.x < 15) p[threadIdx.x] = pal[threadIdx.x];
    __syncthreads();
    int idx = blockIdx.x * blockDim.x + threadIdx.x;
    if (idx >= 8 * RK * DD) return;
    int which = idx / (RK * DD);
    int e = idx - which * (RK * DD);
    const float* srcs[8] = {qd, qu, kd, ku, vd, vu, od, ou};
    const float* s = srcs[which];
    float acc = 0.f;
#pragma unroll
    for (int j = 0; j < 15; j++) acc += p[j] * s[e * 15 + j];
    if (which & 1) g_up[which >> 1][e] = acc;
    else          g_down[which >> 1][e] = acc;
}

// ============================================================
// Kernel 1: W_eff = W + up @ down, written as fp16 hi/lo pair
// ============================================================
__global__ void k_weff(const float* __restrict__ Wq, const float* __restrict__ Wk,
                       const float* __restrict__ Wv, const float* __restrict__ Wo)
{
    const int per_w = DD * DD / 4;
    int idx = blockIdx.x * blockDim.x + threadIdx.x;
    if (idx >= 4 * per_w) return;
    int w = idx / per_w;
    int e4 = idx - w * per_w;
    int o = e4 / (DD / 4);
    int i4 = e4 - o * (DD / 4);
    const float* Ws[4] = {Wq, Wk, Wv, Wo};
    float4 acc = reinterpret_cast<const float4*>(Ws[w])[e4];
#pragma unroll
    for (int r = 0; r < RK; r++) {
        float u = g_up[w][o * RK + r];
        float4 d = reinterpret_cast<const float4*>(&g_down[w][r * DD])[i4];
        acc.x += u * d.x; acc.y += u * d.y; acc.z += u * d.z; acc.w += u * d.w;
    }
    float v[4] = {acc.x, acc.y, acc.z, acc.w};
    reinterpret_cast<uint32_t*>(&g_Whi[w][0])[2*e4]   = pack2(v[0], v[1]);
    reinterpret_cast<uint32_t*>(&g_Whi[w][0])[2*e4+1] = pack2(v[2], v[3]);
    reinterpret_cast<uint32_t*>(&g_Wlo[w][0])[2*e4]   = pack2(res_lo(v[0]), res_lo(v[1]));
    reinterpret_cast<uint32_t*>(&g_Wlo[w][0])[2*e4+1] = pack2(res_lo(v[2]), res_lo(v[3]));
}

// ============================================================
// Kernel 1b: fp32 activation -> fp16 hi only
// ============================================================
__global__ void k_cvtA(const float* __restrict__ src)
{
    int i = blockIdx.x * blockDim.x + threadIdx.x;
    if (i >= NTOK * DD / 4) return;
    float4 a = reinterpret_cast<const float4*>(src)[i];
    reinterpret_cast<uint32_t*>(g_Ah)[2*i]   = pack2(a.x, a.y);
    reinterpret_cast<uint32_t*>(g_Ah)[2*i+1] = pack2(a.z, a.w);
}

// ============================================================
// GEMM core: 128x128 tile, BK=32, 8 warps, 2-pass split fp16
// C = Ah @ (Wh + Wl)^T
// ============================================================
#define BK 32
#define TSTRIDE 80
#define TILEB (128 * TSTRIDE)
#define STAGEB (3 * TILEB)         // Ah, Wh, Wl
#define GEMM_SMEM (2 * STAGEB)
#define NCHUNK (DD / BK)

struct GemmOut {
    float* Cf; const float* bias;
    __half* Ch; __half* Cl;        // Cl may be null (hi-only output)
};

__device__ __forceinline__ void gemm_body(
    const __half* __restrict__ Ah, const __half* __restrict__ Whi,
    const __half* __restrict__ Wlo,
    const GemmOut& o, size_t tileM, size_t tileN, char* smem)
{
    const uint32_t sbase = smem_u32(smem);
    const int tid = threadIdx.x;
    const int lane = tid & 31, wid = tid >> 5;
    const int warp_m = (wid & 3) * 32, warp_n = (wid >> 2) * 64;
    const int K = DD, N = DD;

    const __half* srcs[3] = {Ah, Whi, Wlo};

    auto load_stage = [&](int kc, int s) {
        const int kcol = kc * BK;
        uint32_t dst0 = sbase + s * STAGEB;
#pragma unroll
        for (int i = 0; i < 6; i++) {
            int idx = i * 256 + tid;           // 3 tiles x 128 rows x 4 chunks
            int t = idx >> 9;
            int rem = idx & 511;
            int r = rem >> 2, c = rem & 3;
            size_t grow = (t == 0) ? (tileM + r) : (tileN + r);
            const __half* src = srcs[t] + grow * K + kcol + c * 8;
            cp16(dst0 + t * TILEB + r * TSTRIDE + c * 16, src);
        }
        CP_COMMIT();
    };

    float acc[2][8][4];
#pragma unroll
    for (int mf = 0; mf < 2; mf++)
#pragma unroll
        for (int nf = 0; nf < 8; nf++)
#pragma unroll
            for (int j = 0; j < 4; j++) acc[mf][nf][j] = 0.f;

    load_stage(0, 0);

    const int a_row = warp_m + ((lane >> 3) & 1) * 8 + (lane & 7);
    const uint32_t a_off = (uint32_t)(a_row * TSTRIDE + (lane >> 4) * 16);
    const int b_row = warp_n + ((lane >> 4) & 1) * 8 + (lane & 7);
    const uint32_t b_off = (uint32_t)(b_row * TSTRIDE + ((lane >> 3) & 1) * 16);

    for (int kc = 0; kc < NCHUNK; kc++) {
        const int s = kc & 1;
        if (kc + 1 < NCHUNK) { load_stage(kc + 1, s ^ 1); CP_WAIT(1); }
        else { CP_WAIT(0); }
        __syncthreads();

        const uint32_t stage = sbase + s * STAGEB;
#pragma unroll
        for (int ks = 0; ks < 2; ks++) {
            const uint32_t kb = ks * 32;
            uint32_t ah[2][4];
#pragma unroll
            for (int mf = 0; mf < 2; mf++)
                ldsm4(ah[mf], stage + a_off + mf * (16 * TSTRIDE) + kb);
#pragma unroll
            for (int np = 0; np < 4; np++) {
                uint32_t bh[4], bl[4];
                ldsm4(bh, stage + TILEB + b_off + np * (16 * TSTRIDE) + kb);
                ldsm4(bl, stage + 2 * TILEB + b_off + np * (16 * TSTRIDE) + kb);
#pragma unroll
                for (int mf = 0; mf < 2; mf++) {
#pragma unroll
                    for (int half = 0; half < 2; half++) {
                        float* d = acc[mf][np * 2 + half];
                        mma16816(d, ah[mf], bh + half * 2);
                        mma16816(d, ah[mf], bl + half * 2);
                    }
                }
            }
        }
        __syncthreads();
    }

    const int er = lane >> 2;
    const int ec = (lane & 3) * 2;
#pragma unroll
    for (int mf = 0; mf < 2; mf++) {
        size_t row0 = tileM + warp_m + mf * 16 + er;
#pragma unroll
        for (int nf = 0; nf < 8; nf++) {
            size_t col = tileN + warp_n + nf * 8 + ec;
            float f0 = acc[mf][nf][0], f1 = acc[mf][nf][1];
            float f2 = acc[mf][nf][2], f3 = acc[mf][nf][3];
            if (o.Cf) {
                float bx = 0.f, by = 0.f;
                if (o.bias) { bx = o.bias[col]; by = o.bias[col + 1]; }
                float2 v0 = {f0 + bx, f1 + by};
                float2 v1 = {f2 + bx, f3 + by};
                *reinterpret_cast<float2*>(o.Cf + row0 * N + col) = v0;
                *reinterpret_cast<float2*>(o.Cf + (row0 + 8) * N + col) = v1;
            } else {
                *reinterpret_cast<uint32_t*>(o.Ch + row0 * N + col)       = pack2(f0, f1);
                *reinterpret_cast<uint32_t*>(o.Ch + (row0 + 8) * N + col) = pack2(f2, f3);
                if (o.Cl) {
                    *reinterpret_cast<uint32_t*>(o.Cl + row0 * N + col)       = pack2(res_lo(f0), res_lo(f1));
                    *reinterpret_cast<uint32_t*>(o.Cl + (row0 + 8) * N + col) = pack2(res_lo(f2), res_lo(f3));
                }
            }
        }
    }
}

// ---- fused QKV: grid (N/128, M/128, 3); z selects weight/output ----
__global__ void __launch_bounds__(256, 2) qkv_tc()
{
    extern __shared__ char smem[];
    const int z = blockIdx.z;
    GemmOut o;
    o.Cf = nullptr; o.bias = nullptr;
    o.Ch = (z == 0) ? g_Qh : (z == 1) ? g_Kh : g_Vh;
    o.Cl = (z == 0) ? nullptr : (z == 1) ? g_Kl : g_Vl;   // Q is A-side later: hi only
    gemm_body(g_Ah, g_Whi[z], g_Wlo[z],
              o, (size_t)blockIdx.y * 128, (size_t)blockIdx.x * 128, smem);
}

// ---- AO projection: fp32 out + bias ----
__global__ void __launch_bounds__(256, 2) o_tc(const float* __restrict__ bias,
                                               float* __restrict__ out)
{
    extern __shared__ char smem[];
    GemmOut o;
    o.Cf = out; o.bias = bias; o.Ch = nullptr; o.Cl = nullptr;
    gemm_body(g_AOh, g_Whi[3], g_Wlo[3],
              o, (size_t)blockIdx.y * 128, (size_t)blockIdx.x * 128, smem);
}

// ============================================================
// Kernel 3: flash attention, 2-pass split fp16 FA2
// BQ=128, BK=64, hd=160. 8 warps x 16 rows. grid (16, 8, 2).
// ============================================================
#define AQ_STR 168                 // halves; 336 B row stride
#define AQ_ROWB (AQ_STR * 2)       // 336
#define Q_TILEB (128 * AQ_ROWB)    // 43008 (hi only)
#define KV_TILEB (64 * AQ_ROWB)    // 21504
#define ATTN_SMEM (Q_TILEB + 4 * KV_TILEB)   // 129024

__global__ void __launch_bounds__(256) attn_tc()
{
    extern __shared__ char sm[];
    const uint32_t sb = smem_u32(sm);
    const uint32_t Qh_s = sb;
    const uint32_t KV_s = sb + Q_TILEB;      // Kh, Kl, Vh, Vl contiguous
    const uint32_t Kh_s = KV_s;
    const uint32_t Vh_s = KV_s + 2 * KV_TILEB;

    const int qt = blockIdx.x, h = blockIdx.y, b = blockIdx.z;
    const int tid = threadIdx.x, lane = tid & 31, wid = tid >> 5;
    const float cscale = rsqrtf((float)HDIM) * 1.44269504f;   // attn_scale * log2(e)

    const size_t qtok = (size_t)b * SEQ + (size_t)qt * 128;
    const size_t hoff = (size_t)h * HDIM;

    // ---- load Q tile (hi only): 128 rows x 20 chunks ----
#pragma unroll
    for (int i = 0; i < 10; i++) {
        int idx = i * 256 + tid;
        int r = idx / 20, c = idx - r * 20;
        cp16(Qh_s + r * AQ_ROWB + c * 16, g_Qh + (qtok + r) * DD + hoff + c * 8);
    }
    CP_COMMIT();

    float m0 = -1e30f, m1 = -1e30f, l0 = 0.f, l1 = 0.f;
    float oacc[20][4];
#pragma unroll
    for (int v = 0; v < 20; v++)
#pragma unroll
        for (int j = 0; j < 4; j++) oacc[v][j] = 0.f;

    const uint32_t qa_off = (uint32_t)((wid * 16 + (lane & 15)) * AQ_ROWB + (lane >> 4) * 16);
    const uint32_t kb_lane = (uint32_t)((((lane >> 4) & 1) * 8 + (lane & 7)) * AQ_ROWB + ((lane >> 3) & 1) * 16);
    const uint32_t v_lane = (uint32_t)((lane & 15) * AQ_ROWB + (lane >> 4) * 16);

    for (int kt = 0; kt < SEQ / 64; kt++) {
        const size_t ktok = (size_t)b * SEQ + (size_t)kt * 64;
        {
            const __half* gs[4] = {g_Kh, g_Kl, g_Vh, g_Vl};
#pragma unroll
            for (int i = 0; i < 20; i++) {
                int idx = i * 256 + tid;
                int arr = idx / 1280;
                int rem = idx - arr * 1280;
                int r = rem / 20, c = rem - r * 20;
                cp16(KV_s + arr * KV_TILEB + r * AQ_ROWB + c * 16,
                     gs[arr] + (ktok + r) * DD + hoff + c * 8);
            }
            CP_COMMIT();
            CP_WAIT(0);
        }
        __syncthreads();

        // ---- S = Q K^T : Qh * (Kh + Kl), 2 passes ----
        float sacc[8][4];
#pragma unroll
        for (int nt = 0; nt < 8; nt++)
#pragma unroll
            for (int j = 0; j < 4; j++) sacc[nt][j] = 0.f;

#pragma unroll
        for (int k = 0; k < 10; k++) {
            uint32_t ah[4];
            ldsm4(ah, Qh_s + qa_off + k * 32);
#pragma unroll
            for (int np = 0; np < 4; np++) {
                uint32_t bh[4], bl[4];
                uint32_t kaddr = Kh_s + (uint32_t)(np * 16 * AQ_ROWB) + kb_lane + k * 32;
                ldsm4(bh, kaddr);
                ldsm4(bl, kaddr + KV_TILEB);
#pragma unroll
                for (int half = 0; half < 2; half++) {
                    float* d = sacc[np * 2 + half];
                    mma16816(d, ah, bh + half * 2);
                    mma16816(d, ah, bl + half * 2);
                }
            }
        }

        // ---- online softmax ----
        float mx0 = -1e30f, mx1 = -1e30f;
#pragma unroll
        for (int nt = 0; nt < 8; nt++) {
            sacc[nt][0] *= cscale; sacc[nt][1] *= cscale;
            sacc[nt][2] *= cscale; sacc[nt][3] *= cscale;
            mx0 = fmaxf(mx0, fmaxf(sacc[nt][0], sacc[nt][1]));
            mx1 = fmaxf(mx1, fmaxf(sacc[nt][2], sacc[nt][3]));
        }
        mx0 = fmaxf(mx0, __shfl_xor_sync(0xffffffffu, mx0, 1));
        mx0 = fmaxf(mx0, __shfl_xor_sync(0xffffffffu, mx0, 2));
        mx1 = fmaxf(mx1, __shfl_xor_sync(0xffffffffu, mx1, 1));
        mx1 = fmaxf(mx1, __shfl_xor_sync(0xffffffffu, mx1, 2));
        float nm0 = fmaxf(m0, mx0), nm1 = fmaxf(m1, mx1);
        float al0 = ex2f(m0 - nm0), al1 = ex2f(m1 - nm1);
        m0 = nm0; m1 = nm1;

        float ps0 = 0.f, ps1 = 0.f;
#pragma unroll
        for (int nt = 0; nt < 8; nt++) {
            sacc[nt][0] = ex2f(sacc[nt][0] - nm0);
            sacc[nt][1] = ex2f(sacc[nt][1] - nm0);
            sacc[nt][2] = ex2f(sacc[nt][2] - nm1);
            sacc[nt][3] = ex2f(sacc[nt][3] - nm1);
            ps0 += sacc[nt][0] + sacc[nt][1];
            ps1 += sacc[nt][2] + sacc[nt][3];
        }
        ps0 += __shfl_xor_sync(0xffffffffu, ps0, 1);
        ps0 += __shfl_xor_sync(0xffffffffu, ps0, 2);
        ps1 += __shfl_xor_sync(0xffffffffu, ps1, 1);
        ps1 += __shfl_xor_sync(0xffffffffu, ps1, 2);
        l0 = l0 * al0 + ps0;
        l1 = l1 * al1 + ps1;

#pragma unroll
        for (int v = 0; v < 20; v++) {
            oacc[v][0] *= al0; oacc[v][1] *= al0;
            oacc[v][2] *= al1; oacc[v][3] *= al1;
        }

        // ---- O += P V : Ph * (Vh + Vl), 2 passes ----
#pragma unroll
        for (int kt2 = 0; kt2 < 4; kt2++) {
            const float* p0 = sacc[2 * kt2];
            const float* p1 = sacc[2 * kt2 + 1];
            uint32_t pah[4];
            pah[0] = pack2(p0[0], p0[1]);
            pah[1] = pack2(p0[2], p0[3]);
            pah[2] = pack2(p1[0], p1[1]);
            pah[3] = pack2(p1[2], p1[3]);
#pragma unroll
            for (int vp = 0; vp < 10; vp++) {
                uint32_t bvh[4], bvl[4];
                uint32_t vaddr = Vh_s + (uint32_t)(kt2 * 16 * AQ_ROWB) + v_lane + vp * 32;
                ldsm4t(bvh, vaddr);
                ldsm4t(bvl, vaddr + KV_TILEB);
#pragma unroll
                for (int half = 0; half < 2; half++) {
                    float* d = oacc[vp * 2 + half];
                    mma16816(d, pah, bvh + half * 2);
                    mma16816(d, pah, bvl + half * 2);
                }
            }
        }
        __syncthreads();
    }

    // ---- epilogue: normalize, store fp16 hi (A-side of o-proj) ----
    float inv0 = 1.f / l0, inv1 = 1.f / l1;
    const size_t tok0 = qtok + wid * 16 + (lane >> 2);
    const size_t tok1 = tok0 + 8;
#pragma unroll
    for (int nt = 0; nt < 20; nt++) {
        size_t col = hoff + nt * 8 + (lane & 3) * 2;
        *reinterpret_cast<uint32_t*>(g_AOh + tok0 * DD + col) = pack2(oacc[nt][0] * inv0, oacc[nt][1] * inv0);
        *reinterpret_cast<uint32_t*>(g_AOh + tok1 * DD + col) = pack2(oacc[nt][2] * inv1, oacc[nt][3] * inv1);
    }
}

// ============================================================
// host launcher
// ============================================================
extern "C" void kernel_launch(void* const* d_in, const int* in_sizes, int n_in,
                              void* d_out, int out_size)
{
    const float* x   = (const float*)d_in[0];
    const float* pal = (const float*)d_in[1];
    const float* Wq  = (const float*)d_in[2];
    const float* Wk  = (const float*)d_in[3];
    const float* Wv  = (const float*)d_in[4];
    const float* Wo  = (const float*)d_in[5];
    const float* bo  = (const float*)d_in[6];
    const float* qd  = (const float*)d_in[7];
    const float* qu  = (const float*)d_in[8];
    const float* kd  = (const float*)d_in[9];
    const float* ku  = (const float*)d_in[10];
    const float* vd  = (const float*)d_in[11];
    const float* vu  = (const float*)d_in[12];
    const float* od  = (const float*)d_in[13];
    const float* ou  = (const float*)d_in[14];
    float* out = (float*)d_out;

    cudaFuncSetAttribute(qkv_tc, cudaFuncAttributeMaxDynamicSharedMemorySize, GEMM_SMEM);
    cudaFuncSetAttribute(o_tc, cudaFuncAttributeMaxDynamicSharedMemorySize, GEMM_SMEM);
    cudaFuncSetAttribute(attn_tc, cudaFuncAttributeMaxDynamicSharedMemorySize, ATTN_SMEM);

    // 0) palette contractions
    k_downup<<<(8 * RK * DD + 255) / 256, 256>>>(pal, qd, qu, kd, ku, vd, vu, od, ou);
    // 1) effective weights (LoRA folded) -> fp16 hi/lo
    k_weff<<<(4 * DD * DD / 4 + 255) / 256, 256>>>(Wq, Wk, Wv, Wo);
    // 1b) x -> fp16 hi
    k_cvtA<<<(NTOK * DD / 4 + 255) / 256, 256>>>(x);
    // 2) fused Q,K,V projections (one launch, 960 CTAs)
    dim3 gqkv(DD / 128, NTOK / 128, 3);
    qkv_tc<<<gqkv, 256, GEMM_SMEM>>>();
    // 3) attention -> fp16 hi AO
    dim3 gattn(SEQ / 128, NH, NB);
    attn_tc<<<gattn, 256, ATTN_SMEM>>>();
    // 4) output projection + bias -> fp32 out
    dim3 go(DD / 128, NTOK / 128);
    o_tc<<<go, 256, GEMM_SMEM>>>(bo, out);
}

// round 13
// speedup vs baseline: 6.1456x; 1.0483x over previous
#include <cuda_runtime.h>
#include <cuda_fp16.h>
#include <math.h>
#include <cstdint>

#define DD 1280
#define NH 8
#define HDIM 160
#define RK 4
#define NB 2
#define SEQ 2048
#define NTOK (NB*SEQ)

// ---- scratch (static __device__ arrays; no allocation) ----
__device__ float g_down[4][RK*DD];
__device__ float g_up[4][RK*DD];
__device__ __half g_Whi[4][DD*DD];
__device__ __half g_Wlo[4][DD*DD];
__device__ __half g_Ah[NTOK*DD];        // x, fp16 hi only
__device__ __half g_Qh[NTOK*DD];
__device__ __half g_Kh[NTOK*DD];
__device__ __half g_Kl[NTOK*DD];
__device__ __half g_Vh[NTOK*DD];
__device__ __half g_Vl[NTOK*DD];
__device__ __half g_AOh[NTOK*DD];

// ============================================================
// helpers (family-portable, sm_80+)
// ============================================================
__device__ __forceinline__ uint32_t smem_u32(const void* p) {
    uint32_t a;
    asm("{ .reg .u64 t; cvta.to.shared.u64 t, %1; cvt.u32.u64 %0, t; }" : "=r"(a) : "l"(p));
    return a;
}
__device__ __forceinline__ void cp16(uint32_t dst, const void* src) {
    asm volatile("cp.async.cg.shared.global [%0], [%1], 16;" :: "r"(dst), "l"(src) : "memory");
}
#define CP_COMMIT() asm volatile("cp.async.commit_group;" ::: "memory")
#define CP_WAIT(n)  asm volatile("cp.async.wait_group %0;" :: "n"(n) : "memory")

__device__ __forceinline__ void ldsm4(uint32_t* r, uint32_t addr) {
    asm volatile("ldmatrix.sync.aligned.m8n8.x4.shared.b16 {%0,%1,%2,%3}, [%4];"
        : "=r"(r[0]), "=r"(r[1]), "=r"(r[2]), "=r"(r[3]) : "r"(addr));
}
__device__ __forceinline__ void ldsm4t(uint32_t* r, uint32_t addr) {
    asm volatile("ldmatrix.sync.aligned.m8n8.x4.trans.shared.b16 {%0,%1,%2,%3}, [%4];"
        : "=r"(r[0]), "=r"(r[1]), "=r"(r[2]), "=r"(r[3]) : "r"(addr));
}
__device__ __forceinline__ void mma16816(float* d, const uint32_t* a, const uint32_t* b) {
    asm volatile(
        "mma.sync.aligned.m16n8k16.row.col.f32.f16.f16.f32 "
        "{%0,%1,%2,%3}, {%4,%5,%6,%7}, {%8,%9}, {%0,%1,%2,%3};"
        : "+f"(d[0]), "+f"(d[1]), "+f"(d[2]), "+f"(d[3])
        : "r"(a[0]), "r"(a[1]), "r"(a[2]), "r"(a[3]), "r"(b[0]), "r"(b[1]));
}
__device__ __forceinline__ float ex2f(float x) {
    float y; asm("ex2.approx.f32 %0, %1;" : "=f"(y) : "f"(x)); return y;
}
__device__ __forceinline__ uint32_t pack2(float a, float b) {
    __half2 v = __floats2half2_rn(a, b);
    return reinterpret_cast<uint32_t&>(v);
}
__device__ __forceinline__ float res_lo(float f) {
    return f - __half2float(__float2half_rn(f));
}

// ============================================================
// Kernel 0: contract palette into down/up vectors for 4 LoRAs
// ============================================================
__global__ void k_downup(const float* __restrict__ pal,
    const float* __restrict__ qd, const float* __restrict__ qu,
    const float* __restrict__ kd, const float* __restrict__ ku,
    const float* __restrict__ vd, const float* __restrict__ vu,
    const float* __restrict__ od, const float* __restrict__ ou)
{
    __shared__ float p[15];
    if (threadIdx.x < 15) p[threadIdx.x] = pal[threadIdx.x];
    __syncthreads();
    int idx = blockIdx.x * blockDim.x + threadIdx.x;
    if (idx >= 8 * RK * DD) return;
    int which = idx / (RK * DD);
    int e = idx - which * (RK * DD);
    const float* srcs[8] = {qd, qu, kd, ku, vd, vu, od, ou};
    const float* s = srcs[which];
    float acc = 0.f;
#pragma unroll
    for (int j = 0; j < 15; j++) acc += p[j] * s[e * 15 + j];
    if (which & 1) g_up[which >> 1][e] = acc;
    else          g_down[which >> 1][e] = acc;
}

// ============================================================
// Kernel 1: W_eff = W + up @ down, written as fp16 hi/lo pair
// ============================================================
__global__ void k_weff(const float* __restrict__ Wq, const float* __restrict__ Wk,
                       const float* __restrict__ Wv, const float* __restrict__ Wo)
{
    const int per_w = DD * DD / 4;
    int idx = blockIdx.x * blockDim.x + threadIdx.x;
    if (idx >= 4 * per_w) return;
    int w = idx / per_w;
    int e4 = idx - w * per_w;
    int o = e4 / (DD / 4);
    int i4 = e4 - o * (DD / 4);
    const float* Ws[4] = {Wq, Wk, Wv, Wo};
    float4 acc = reinterpret_cast<const float4*>(Ws[w])[e4];
#pragma unroll
    for (int r = 0; r < RK; r++) {
        float u = g_up[w][o * RK + r];
        float4 d = reinterpret_cast<const float4*>(&g_down[w][r * DD])[i4];
        acc.x += u * d.x; acc.y += u * d.y; acc.z += u * d.z; acc.w += u * d.w;
    }
    float v[4] = {acc.x, acc.y, acc.z, acc.w};
    reinterpret_cast<uint32_t*>(&g_Whi[w][0])[2*e4]   = pack2(v[0], v[1]);
    reinterpret_cast<uint32_t*>(&g_Whi[w][0])[2*e4+1] = pack2(v[2], v[3]);
    reinterpret_cast<uint32_t*>(&g_Wlo[w][0])[2*e4]   = pack2(res_lo(v[0]), res_lo(v[1]));
    reinterpret_cast<uint32_t*>(&g_Wlo[w][0])[2*e4+1] = pack2(res_lo(v[2]), res_lo(v[3]));
}

// ============================================================
// Kernel 1b: fp32 activation -> fp16 hi only
// ============================================================
__global__ void k_cvtA(const float* __restrict__ src)
{
    int i = blockIdx.x * blockDim.x + threadIdx.x;
    if (i >= NTOK * DD / 4) return;
    float4 a = reinterpret_cast<const float4*>(src)[i];
    reinterpret_cast<uint32_t*>(g_Ah)[2*i]   = pack2(a.x, a.y);
    reinterpret_cast<uint32_t*>(g_Ah)[2*i+1] = pack2(a.z, a.w);
}

// ============================================================
// GEMM core: 128x128 tile, BK=32, 8 warps, 2-pass split fp16
// C = Ah @ (Wh + Wl)^T
// ============================================================
#define BK 32
#define TSTRIDE 80
#define TILEB (128 * TSTRIDE)
#define STAGEB (3 * TILEB)         // Ah, Wh, Wl
#define GEMM_SMEM (2 * STAGEB)
#define NCHUNK (DD / BK)

struct GemmOut {
    float* Cf; const float* bias;
    __half* Ch; __half* Cl;        // Cl may be null (hi-only output)
};

__device__ __forceinline__ void gemm_body(
    const __half* __restrict__ Ah, const __half* __restrict__ Whi,
    const __half* __restrict__ Wlo,
    const GemmOut& o, size_t tileM, size_t tileN, char* smem)
{
    const uint32_t sbase = smem_u32(smem);
    const int tid = threadIdx.x;
    const int lane = tid & 31, wid = tid >> 5;
    const int warp_m = (wid & 3) * 32, warp_n = (wid >> 2) * 64;
    const int K = DD, N = DD;

    const __half* srcs[3] = {Ah, Whi, Wlo};

    auto load_stage = [&](int kc, int s) {
        const int kcol = kc * BK;
        uint32_t dst0 = sbase + s * STAGEB;
#pragma unroll
        for (int i = 0; i < 6; i++) {
            int idx = i * 256 + tid;           // 3 tiles x 128 rows x 4 chunks
            int t = idx >> 9;
            int rem = idx & 511;
            int r = rem >> 2, c = rem & 3;
            size_t grow = (t == 0) ? (tileM + r) : (tileN + r);
            const __half* src = srcs[t] + grow * K + kcol + c * 8;
            cp16(dst0 + t * TILEB + r * TSTRIDE + c * 16, src);
        }
        CP_COMMIT();
    };

    float acc[2][8][4];
#pragma unroll
    for (int mf = 0; mf < 2; mf++)
#pragma unroll
        for (int nf = 0; nf < 8; nf++)
#pragma unroll
            for (int j = 0; j < 4; j++) acc[mf][nf][j] = 0.f;

    load_stage(0, 0);

    const int a_row = warp_m + ((lane >> 3) & 1) * 8 + (lane & 7);
    const uint32_t a_off = (uint32_t)(a_row * TSTRIDE + (lane >> 4) * 16);
    const int b_row = warp_n + ((lane >> 4) & 1) * 8 + (lane & 7);
    const uint32_t b_off = (uint32_t)(b_row * TSTRIDE + ((lane >> 3) & 1) * 16);

    for (int kc = 0; kc < NCHUNK; kc++) {
        const int s = kc & 1;
        if (kc + 1 < NCHUNK) { load_stage(kc + 1, s ^ 1); CP_WAIT(1); }
        else { CP_WAIT(0); }
        __syncthreads();

        const uint32_t stage = sbase + s * STAGEB;
#pragma unroll
        for (int ks = 0; ks < 2; ks++) {
            const uint32_t kb = ks * 32;
            uint32_t ah[2][4];
#pragma unroll
            for (int mf = 0; mf < 2; mf++)
                ldsm4(ah[mf], stage + a_off + mf * (16 * TSTRIDE) + kb);
#pragma unroll
            for (int np = 0; np < 4; np++) {
                uint32_t bh[4], bl[4];
                ldsm4(bh, stage + TILEB + b_off + np * (16 * TSTRIDE) + kb);
                ldsm4(bl, stage + 2 * TILEB + b_off + np * (16 * TSTRIDE) + kb);
#pragma unroll
                for (int mf = 0; mf < 2; mf++) {
#pragma unroll
                    for (int half = 0; half < 2; half++) {
                        float* d = acc[mf][np * 2 + half];
                        mma16816(d, ah[mf], bh + half * 2);
                        mma16816(d, ah[mf], bl + half * 2);
                    }
                }
            }
        }
        __syncthreads();
    }

    const int er = lane >> 2;
    const int ec = (lane & 3) * 2;
#pragma unroll
    for (int mf = 0; mf < 2; mf++) {
        size_t row0 = tileM + warp_m + mf * 16 + er;
#pragma unroll
        for (int nf = 0; nf < 8; nf++) {
            size_t col = tileN + warp_n + nf * 8 + ec;
            float f0 = acc[mf][nf][0], f1 = acc[mf][nf][1];
            float f2 = acc[mf][nf][2], f3 = acc[mf][nf][3];
            if (o.Cf) {
                float bx = 0.f, by = 0.f;
                if (o.bias) { bx = o.bias[col]; by = o.bias[col + 1]; }
                float2 v0 = {f0 + bx, f1 + by};
                float2 v1 = {f2 + bx, f3 + by};
                *reinterpret_cast<float2*>(o.Cf + row0 * N + col) = v0;
                *reinterpret_cast<float2*>(o.Cf + (row0 + 8) * N + col) = v1;
            } else {
                *reinterpret_cast<uint32_t*>(o.Ch + row0 * N + col)       = pack2(f0, f1);
                *reinterpret_cast<uint32_t*>(o.Ch + (row0 + 8) * N + col) = pack2(f2, f3);
                if (o.Cl) {
                    *reinterpret_cast<uint32_t*>(o.Cl + row0 * N + col)       = pack2(res_lo(f0), res_lo(f1));
                    *reinterpret_cast<uint32_t*>(o.Cl + (row0 + 8) * N + col) = pack2(res_lo(f2), res_lo(f3));
                }
            }
        }
    }
}

// ---- fused QKV: grid (N/128, M/128, 3); z selects weight/output ----
__global__ void __launch_bounds__(256, 2) qkv_tc()
{
    extern __shared__ char smem[];
    const int z = blockIdx.z;
    GemmOut o;
    o.Cf = nullptr; o.bias = nullptr;
    o.Ch = (z == 0) ? g_Qh : (z == 1) ? g_Kh : g_Vh;
    o.Cl = (z == 0) ? nullptr : (z == 1) ? g_Kl : g_Vl;
    gemm_body(g_Ah, g_Whi[z], g_Wlo[z],
              o, (size_t)blockIdx.y * 128, (size_t)blockIdx.x * 128, smem);
}

// ---- AO projection: fp32 out + bias ----
__global__ void __launch_bounds__(256, 2) o_tc(const float* __restrict__ bias,
                                               float* __restrict__ out)
{
    extern __shared__ char smem[];
    GemmOut o;
    o.Cf = out; o.bias = bias; o.Ch = nullptr; o.Cl = nullptr;
    gemm_body(g_AOh, g_Whi[3], g_Wlo[3],
              o, (size_t)blockIdx.y * 128, (size_t)blockIdx.x * 128, smem);
}

// ============================================================
// Kernel 3: flash attention, 2-pass split fp16 FA2, software
// pipelined: K double-buffered, V load overlapped with QK.
// BQ=128, BK=64, hd=160. 8 warps x 16 rows. grid (16, 8, 2).
// ============================================================
#define AQ_ROWB 336                      // 168 halves per row
#define Q_TILEB (128 * AQ_ROWB)          // 43008
#define K_ARRB (64 * AQ_ROWB)            // 21504 (one of hi/lo)
#define K_STAGEB (2 * K_ARRB)            // 43008 (Kh + Kl)
#define ATTN_SMEM (Q_TILEB + 2 * K_STAGEB + K_STAGEB)   // 172032

__global__ void __launch_bounds__(256) attn_tc()
{
    extern __shared__ char sm[];
    const uint32_t sb = smem_u32(sm);
    const uint32_t Q_s = sb;
    const uint32_t K_s0 = sb + Q_TILEB;            // two stages of (Kh,Kl)
    const uint32_t V_s = sb + Q_TILEB + 2 * K_STAGEB;   // (Vh,Vl)

    const int qt = blockIdx.x, h = blockIdx.y, b = blockIdx.z;
    const int tid = threadIdx.x, lane = tid & 31, wid = tid >> 5;
    const float cscale = rsqrtf((float)HDIM) * 1.44269504f;   // attn_scale * log2(e)

    const size_t qtok = (size_t)b * SEQ + (size_t)qt * 128;
    const size_t hoff = (size_t)h * HDIM;

    auto load_K = [&](int kt, int s) {
        const size_t ktok = (size_t)b * SEQ + (size_t)kt * 64;
        uint32_t dst = K_s0 + (uint32_t)s * K_STAGEB;
#pragma unroll
        for (int i = 0; i < 10; i++) {
            int idx = i * 256 + tid;
            int arr = idx / 1280;
            int rem = idx - arr * 1280;
            int r = rem / 20, c = rem - r * 20;
            cp16(dst + arr * K_ARRB + r * AQ_ROWB + c * 16,
                 (arr ? g_Kl : g_Kh) + (ktok + r) * DD + hoff + c * 8);
        }
    };
    auto load_V = [&](int kt) {
        const size_t ktok = (size_t)b * SEQ + (size_t)kt * 64;
#pragma unroll
        for (int i = 0; i < 10; i++) {
            int idx = i * 256 + tid;
            int arr = idx / 1280;
            int rem = idx - arr * 1280;
            int r = rem / 20, c = rem - r * 20;
            cp16(V_s + arr * K_ARRB + r * AQ_ROWB + c * 16,
                 (arr ? g_Vl : g_Vh) + (ktok + r) * DD + hoff + c * 8);
        }
    };

    // ---- prologue: Q tile + K(0) as group G0 ----
#pragma unroll
    for (int i = 0; i < 10; i++) {
        int idx = i * 256 + tid;
        int r = idx / 20, c = idx - r * 20;
        cp16(Q_s + r * AQ_ROWB + c * 16, g_Qh + (qtok + r) * DD + hoff + c * 8);
    }
    load_K(0, 0);
    CP_COMMIT();

    float m0 = -1e30f, m1 = -1e30f, l0 = 0.f, l1 = 0.f;
    float oacc[20][4];
#pragma unroll
    for (int v = 0; v < 20; v++)
#pragma unroll
        for (int j = 0; j < 4; j++) oacc[v][j] = 0.f;

    const uint32_t qa_off = (uint32_t)((wid * 16 + (lane & 15)) * AQ_ROWB + (lane >> 4) * 16);
    const uint32_t kb_lane = (uint32_t)((((lane >> 4) & 1) * 8 + (lane & 7)) * AQ_ROWB + ((lane >> 3) & 1) * 16);
    const uint32_t v_lane = (uint32_t)((lane & 15) * AQ_ROWB + (lane >> 4) * 16);

    for (int kt = 0; kt < SEQ / 64; kt++) {
        // issue V(kt); prefetch K(kt+1) into other stage
        load_V(kt);
        CP_COMMIT();
        if (kt + 1 < SEQ / 64) load_K(kt + 1, (kt + 1) & 1);
        CP_COMMIT();                     // possibly-empty group keeps counts uniform

        CP_WAIT(2);                      // K(kt) (and Q) resident
        __syncthreads();

        // ---- S = Q K^T : Qh * (Kh + Kl), 2 passes ----
        const uint32_t Kst = K_s0 + (uint32_t)(kt & 1) * K_STAGEB;
        float sacc[8][4];
#pragma unroll
        for (int nt = 0; nt < 8; nt++)
#pragma unroll
            for (int j = 0; j < 4; j++) sacc[nt][j] = 0.f;

#pragma unroll
        for (int k = 0; k < 10; k++) {
            uint32_t ah[4];
            ldsm4(ah, Q_s + qa_off + k * 32);
#pragma unroll
            for (int np = 0; np < 4; np++) {
                uint32_t bh[4], bl[4];
                uint32_t kaddr = Kst + (uint32_t)(np * 16 * AQ_ROWB) + kb_lane + k * 32;
                ldsm4(bh, kaddr);
                ldsm4(bl, kaddr + K_ARRB);
#pragma unroll
                for (int half = 0; half < 2; half++) {
                    float* d = sacc[np * 2 + half];
                    mma16816(d, ah, bh + half * 2);
                    mma16816(d, ah, bl + half * 2);
                }
            }
        }

        // ---- online softmax ----
        float mx0 = -1e30f, mx1 = -1e30f;
#pragma unroll
        for (int nt = 0; nt < 8; nt++) {
            sacc[nt][0] *= cscale; sacc[nt][1] *= cscale;
            sacc[nt][2] *= cscale; sacc[nt][3] *= cscale;
            mx0 = fmaxf(mx0, fmaxf(sacc[nt][0], sacc[nt][1]));
            mx1 = fmaxf(mx1, fmaxf(sacc[nt][2], sacc[nt][3]));
        }
        mx0 = fmaxf(mx0, __shfl_xor_sync(0xffffffffu, mx0, 1));
        mx0 = fmaxf(mx0, __shfl_xor_sync(0xffffffffu, mx0, 2));
        mx1 = fmaxf(mx1, __shfl_xor_sync(0xffffffffu, mx1, 1));
        mx1 = fmaxf(mx1, __shfl_xor_sync(0xffffffffu, mx1, 2));
        float nm0 = fmaxf(m0, mx0), nm1 = fmaxf(m1, mx1);
        float al0 = ex2f(m0 - nm0), al1 = ex2f(m1 - nm1);
        m0 = nm0; m1 = nm1;

        float ps0 = 0.f, ps1 = 0.f;
#pragma unroll
        for (int nt = 0; nt < 8; nt++) {
            sacc[nt][0] = ex2f(sacc[nt][0] - nm0);
            sacc[nt][1] = ex2f(sacc[nt][1] - nm0);
            sacc[nt][2] = ex2f(sacc[nt][2] - nm1);
            sacc[nt][3] = ex2f(sacc[nt][3] - nm1);
            ps0 += sacc[nt][0] + sacc[nt][1];
            ps1 += sacc[nt][2] + sacc[nt][3];
        }
        ps0 += __shfl_xor_sync(0xffffffffu, ps0, 1);
        ps0 += __shfl_xor_sync(0xffffffffu, ps0, 2);
        ps1 += __shfl_xor_sync(0xffffffffu, ps1, 1);
        ps1 += __shfl_xor_sync(0xffffffffu, ps1, 2);
        l0 = l0 * al0 + ps0;
        l1 = l1 * al1 + ps1;

#pragma unroll
        for (int v = 0; v < 20; v++) {
            oacc[v][0] *= al0; oacc[v][1] *= al0;
            oacc[v][2] *= al1; oacc[v][3] *= al1;
        }

        CP_WAIT(1);                      // V(kt) resident (K(kt+1) may still fly)
        __syncthreads();

        // ---- O += P V : Ph * (Vh + Vl), 2 passes ----
#pragma unroll
        for (int kt2 = 0; kt2 < 4; kt2++) {
            const float* p0 = sacc[2 * kt2];
            const float* p1 = sacc[2 * kt2 + 1];
            uint32_t pah[4];
            pah[0] = pack2(p0[0], p0[1]);
            pah[1] = pack2(p0[2], p0[3]);
            pah[2] = pack2(p1[0], p1[1]);
            pah[3] = pack2(p1[2], p1[3]);
#pragma unroll
            for (int vp = 0; vp < 10; vp++) {
                uint32_t bvh[4], bvl[4];
                uint32_t vaddr = V_s + (uint32_t)(kt2 * 16 * AQ_ROWB) + v_lane + vp * 32;
                ldsm4t(bvh, vaddr);
                ldsm4t(bvl, vaddr + K_ARRB);
#pragma unroll
                for (int half = 0; half < 2; half++) {
                    float* d = oacc[vp * 2 + half];
                    mma16816(d, pah, bvh + half * 2);
                    mma16816(d, pah, bvl + half * 2);
                }
            }
        }
        __syncthreads();                 // PV reads done before next V overwrite
    }

    // ---- epilogue: normalize, store fp16 hi (A-side of o-proj) ----
    float inv0 = 1.f / l0, inv1 = 1.f / l1;
    const size_t tok0 = qtok + wid * 16 + (lane >> 2);
    const size_t tok1 = tok0 + 8;
#pragma unroll
    for (int nt = 0; nt < 20; nt++) {
        size_t col = hoff + nt * 8 + (lane & 3) * 2;
        *reinterpret_cast<uint32_t*>(g_AOh + tok0 * DD + col) = pack2(oacc[nt][0] * inv0, oacc[nt][1] * inv0);
        *reinterpret_cast<uint32_t*>(g_AOh + tok1 * DD + col) = pack2(oacc[nt][2] * inv1, oacc[nt][3] * inv1);
    }
}

// ============================================================
// host launcher
// ============================================================
extern "C" void kernel_launch(void* const* d_in, const int* in_sizes, int n_in,
                              void* d_out, int out_size)
{
    const float* x   = (const float*)d_in[0];
    const float* pal = (const float*)d_in[1];
    const float* Wq  = (const float*)d_in[2];
    const float* Wk  = (const float*)d_in[3];
    const float* Wv  = (const float*)d_in[4];
    const float* Wo  = (const float*)d_in[5];
    const float* bo  = (const float*)d_in[6];
    const float* qd  = (const float*)d_in[7];
    const float* qu  = (const float*)d_in[8];
    const float* kd  = (const float*)d_in[9];
    const float* ku  = (const float*)d_in[10];
    const float* vd  = (const float*)d_in[11];
    const float* vu  = (const float*)d_in[12];
    const float* od  = (const float*)d_in[13];
    const float* ou  = (const float*)d_in[14];
    float* out = (float*)d_out;

    cudaFuncSetAttribute(qkv_tc, cudaFuncAttributeMaxDynamicSharedMemorySize, GEMM_SMEM);
    cudaFuncSetAttribute(o_tc, cudaFuncAttributeMaxDynamicSharedMemorySize, GEMM_SMEM);
    cudaFuncSetAttribute(attn_tc, cudaFuncAttributeMaxDynamicSharedMemorySize, ATTN_SMEM);

    // 0) palette contractions
    k_downup<<<(8 * RK * DD + 255) / 256, 256>>>(pal, qd, qu, kd, ku, vd, vu, od, ou);
    // 1) effective weights (LoRA folded) -> fp16 hi/lo
    k_weff<<<(4 * DD * DD / 4 + 255) / 256, 256>>>(Wq, Wk, Wv, Wo);
    // 1b) x -> fp16 hi
    k_cvtA<<<(NTOK * DD / 4 + 255) / 256, 256>>>(x);
    // 2) fused Q,K,V projections (one launch, 960 CTAs)
    dim3 gqkv(DD / 128, NTOK / 128, 3);
    qkv_tc<<<gqkv, 256, GEMM_SMEM>>>();
    // 3) attention (pipelined) -> fp16 hi AO
    dim3 gattn(SEQ / 128, NH, NB);
    attn_tc<<<gattn, 256, ATTN_SMEM>>>();
    // 4) output projection + bias -> fp32 out
    dim3 go(DD / 128, NTOK / 128);
    o_tc<<<go, 256, GEMM_SMEM>>>(bo, out);
}